// round 1
// baseline (speedup 1.0000x reference)
#include <cuda_runtime.h>
#include <math.h>

#define N_PTS   32400
#define C_DIM   512
#define NCLS    19
#define KNN     9

#define BM 128
#define BN 128
#define BK 16
#define NTHREADS 256
#define NKCHUNK (C_DIM / BK)   // 32

// ---------------- scratch (device globals: no allocation allowed) ----------
__device__ float g_sq[N_PTS];
__device__ int   g_label[N_PTS];

// ---------------- preprocessing: sq norms + argmax labels ------------------
__global__ void prep_kernel(const float* __restrict__ feats,
                            const float* __restrict__ outs) {
    int n = blockIdx.x * blockDim.x + threadIdx.x;
    if (n >= N_PTS) return;
    float s = 0.f;
#pragma unroll 8
    for (int c = 0; c < C_DIM; c++) {
        float v = feats[(size_t)c * N_PTS + n];
        s = fmaf(v, v, s);
    }
    g_sq[n] = s;

    float best = outs[n];
    int bl = 0;
#pragma unroll
    for (int c = 1; c < NCLS; c++) {
        float v = outs[(size_t)c * N_PTS + n];
        if (v > best) { best = v; bl = c; }
    }
    g_label[n] = bl;
}

// ---------------- fused GEMM + top-9 + entropy -----------------------------
// Shared memory: GEMM A/B tiles union'd with the distance staging buffer
// (they are live in disjoint phases, separated by __syncthreads).
union __align__(16) SmemU {
    struct { float As[BK][BM]; float Bs[BK][BN]; } g;  // 16 KB
    float Ds[BN / 2][BM + 4];                          // 64 x 132 x 4 = 33 KB
};

__device__ __forceinline__ void ldg_chunk(const float* __restrict__ feats,
                                          int c0, int q0, int j0, int tid,
                                          float4 ra[2], float4 rb[2]) {
#pragma unroll
    for (int r = 0; r < 2; r++) {
        int f   = tid + r * NTHREADS;     // 512 float4 per operand chunk
        int row = f >> 5;                 // 0..15
        int col = (f & 31) * 4;           // 0..124
        size_t base = (size_t)(c0 + row) * N_PTS;
        int qa = q0 + col;
        int qb = j0 + col;
        ra[r] = (qa < N_PTS) ? *(const float4*)&feats[base + qa]
                             : make_float4(0.f, 0.f, 0.f, 0.f);
        rb[r] = (qb < N_PTS) ? *(const float4*)&feats[base + qb]
                             : make_float4(0.f, 0.f, 0.f, 0.f);
    }
}

__device__ __forceinline__ void sts_chunk(SmemU& sm, int tid,
                                          const float4 ra[2], const float4 rb[2]) {
#pragma unroll
    for (int r = 0; r < 2; r++) {
        int f   = tid + r * NTHREADS;
        int row = f >> 5;
        int col = (f & 31) * 4;
        *(float4*)&sm.g.As[row][col] = ra[r];
        *(float4*)&sm.g.Bs[row][col] = rb[r];
    }
}

__global__ __launch_bounds__(NTHREADS)
void knn_entropy_kernel(const float* __restrict__ feats,
                        float* __restrict__ out) {
    __shared__ SmemU sm;
    __shared__ float s_sqq[BM];
    __shared__ float s_sqc[BN];

    const int tid = threadIdx.x;
    const int tx  = tid & 15;   // candidate dim (8 cols each)
    const int ty  = tid >> 4;   // query dim     (8 rows each)
    const int q0  = blockIdx.x * BM;
    const int mvalid = min(BM, N_PTS - q0);

    if (tid < BM) {
        int q = q0 + tid;
        s_sqq[tid] = (q < N_PTS) ? g_sq[q] : 0.f;
    }

    // running top-9 per owner thread (tid < 128, one query each)
    float kd[KNN];
    int   ki[KNN];
#pragma unroll
    for (int t = 0; t < KNN; t++) { kd[t] = INFINITY; ki[t] = 0; }
    float kmax = INFINITY;
    int   kpos = 0;

    for (int j0 = 0; j0 < N_PTS; j0 += BN) {
        if (tid < BN) {
            int j = j0 + tid;
            s_sqc[tid] = (j < N_PTS) ? g_sq[j] : 0.f;
        }

        float acc[8][8];
#pragma unroll
        for (int i = 0; i < 8; i++)
#pragma unroll
            for (int j = 0; j < 8; j++) acc[i][j] = 0.f;

        float4 ra[2], rb[2];
        ldg_chunk(feats, 0, q0, j0, tid, ra, rb);
        sts_chunk(sm, tid, ra, rb);          // prev-iter scan done (synced below)
        __syncthreads();

        for (int kc = 0; kc < NKCHUNK; kc++) {
            if (kc + 1 < NKCHUNK)
                ldg_chunk(feats, (kc + 1) * BK, q0, j0, tid, ra, rb);
#pragma unroll
            for (int kk = 0; kk < BK; kk++) {
                float4 a0 = *(const float4*)&sm.g.As[kk][ty * 8];
                float4 a1 = *(const float4*)&sm.g.As[kk][ty * 8 + 4];
                float4 b0 = *(const float4*)&sm.g.Bs[kk][tx * 8];
                float4 b1 = *(const float4*)&sm.g.Bs[kk][tx * 8 + 4];
                float a[8] = {a0.x, a0.y, a0.z, a0.w, a1.x, a1.y, a1.z, a1.w};
                float b[8] = {b0.x, b0.y, b0.z, b0.w, b1.x, b1.y, b1.z, b1.w};
#pragma unroll
                for (int i = 0; i < 8; i++)
#pragma unroll
                    for (int j = 0; j < 8; j++)
                        acc[i][j] = fmaf(a[i], b[j], acc[i][j]);
            }
            __syncthreads();
            if (kc + 1 < NKCHUNK) {
                sts_chunk(sm, tid, ra, rb);
                __syncthreads();
            }
        }

        // distances -> smem (transposed, two 64-candidate halves), then scan
#pragma unroll
        for (int h = 0; h < 2; h++) {
            if ((tx >> 3) == h) {
                int txh = tx & 7;
#pragma unroll
                for (int j = 0; j < 8; j++) {
                    int nrel = txh * 8 + j;
                    float sc = s_sqc[h * 64 + nrel];
                    float4 v0, v1;
                    v0.x = s_sqq[ty * 8 + 0] + sc - 2.f * acc[0][j];
                    v0.y = s_sqq[ty * 8 + 1] + sc - 2.f * acc[1][j];
                    v0.z = s_sqq[ty * 8 + 2] + sc - 2.f * acc[2][j];
                    v0.w = s_sqq[ty * 8 + 3] + sc - 2.f * acc[3][j];
                    v1.x = s_sqq[ty * 8 + 4] + sc - 2.f * acc[4][j];
                    v1.y = s_sqq[ty * 8 + 5] + sc - 2.f * acc[5][j];
                    v1.z = s_sqq[ty * 8 + 6] + sc - 2.f * acc[6][j];
                    v1.w = s_sqq[ty * 8 + 7] + sc - 2.f * acc[7][j];
                    *(float4*)&sm.Ds[nrel][ty * 8]     = v0;
                    *(float4*)&sm.Ds[nrel][ty * 8 + 4] = v1;
                }
            }
            __syncthreads();
            if (tid < mvalid) {
                int nlim  = min(64, N_PTS - j0 - h * 64);
                int jbase = j0 + h * 64;
                for (int nr = 0; nr < nlim; nr++) {
                    float d = sm.Ds[nr][tid];
                    if (d < kmax) {           // strict <: ties keep lower index
                        kd[kpos] = d;
                        ki[kpos] = jbase + nr;
                        kmax = kd[0]; kpos = 0;
#pragma unroll
                        for (int t = 1; t < KNN; t++)
                            if (kd[t] > kmax) { kmax = kd[t]; kpos = t; }
                    }
                }
            }
            __syncthreads();
        }
    }

    // entropy of the 9 neighbor labels
    if (tid < mvalid) {
        int cnt[NCLS];
#pragma unroll
        for (int c = 0; c < NCLS; c++) cnt[c] = 0;
#pragma unroll
        for (int t = 0; t < KNN; t++) cnt[g_label[ki[t]]]++;
        float s = 0.f;
#pragma unroll
        for (int c = 0; c < NCLS; c++) {
            if (cnt[c] > 0) {
                float p = (float)cnt[c] * (1.f / 9.f);
                s -= p * logf(p + 1e-6f);
            }
        }
        out[q0 + tid] = s * (1.f / logf(19.f));
    }
}

// ---------------- launch ---------------------------------------------------
extern "C" void kernel_launch(void* const* d_in, const int* in_sizes, int n_in,
                              void* d_out, int out_size) {
    const float* feats = (const float*)d_in[0];  // [512, 32400] == F^T
    const float* outs  = (const float*)d_in[1];  // [19, 32400]
    float* out = (float*)d_out;                  // 1080*1920 floats

    cudaMemsetAsync(out, 0, (size_t)out_size * sizeof(float), 0);
    prep_kernel<<<(N_PTS + 255) / 256, 256>>>(feats, outs);
    knn_entropy_kernel<<<(N_PTS + BM - 1) / BM, NTHREADS>>>(feats, out);
}

// round 3
// speedup vs baseline: 1.4951x; 1.4951x over previous
#include <cuda_runtime.h>
#include <cuda_fp16.h>
#include <math.h>
#include <stdint.h>

#define N_PTS 32400
#define N_PAD 32512            // 127*256 = 254*128
#define C_DIM 512
#define NCLS  19
#define KNN   9

#define MT 256                 // queries per CTA
#define NT 128                 // candidates per j-tile
#define KC 64                  // fp16 elems per K chunk (128B rows)
#define NCHUNK (C_DIM / KC)    // 8
#define NJT  (N_PAD / NT)      // 254
#define NCTAS (N_PAD / MT)     // 127
#define NTH 512

// smem layout (byte offsets from 1024-aligned base)
// stage: A 2 planes x 256 x 128B = 65536 ; B 2 planes x 128 x 128B = 32768
#define STAGE_BYTES 98304
#define SM_STAGE0 0
#define SM_STAGE1 STAGE_BYTES
#define SM_TOP    (2 * STAGE_BYTES)          // 196608: kd 256*12*4, then ki 256*12*4
#define SM_SQC    (SM_TOP + 2 * 12288)       // 221184: 128 floats
#define DYNSMEM   (SM_SQC + 512 + 1024)      // + alignment slack
#define DSTRIDE   260                        // dist_s row stride (floats)

// ---------------- device globals ----------------
__device__ __half g_hi[(size_t)N_PAD * C_DIM];
__device__ __half g_lo[(size_t)N_PAD * C_DIM];
__device__ float  g_sq[N_PAD];
__device__ int    g_label[N_PTS];

// ---------------- helpers ----------------
__device__ __forceinline__ uint32_t smem_u32(const void* p) {
    uint32_t a;
    asm("{ .reg .u64 t; cvta.to.shared.u64 t, %1; cvt.u32.u64 %0, t; }" : "=r"(a) : "l"(p));
    return a;
}
__device__ __forceinline__ void cp_async16(uint32_t dst, const void* src) {
    asm volatile("cp.async.cg.shared.global [%0], [%1], 16;"
                 :: "r"(dst), "l"(__cvta_generic_to_global(src)) : "memory");
}
__device__ __forceinline__ void cp_commit() {
    asm volatile("cp.async.commit_group;" ::: "memory");
}
__device__ __forceinline__ void ldsm_x4(uint32_t* r, uint32_t a) {
    asm volatile("ldmatrix.sync.aligned.m8n8.x4.shared.b16 {%0,%1,%2,%3}, [%4];"
                 : "=r"(r[0]), "=r"(r[1]), "=r"(r[2]), "=r"(r[3]) : "r"(a));
}
__device__ __forceinline__ void ldsm_x2(uint32_t* r, uint32_t a) {
    asm volatile("ldmatrix.sync.aligned.m8n8.x2.shared.b16 {%0,%1}, [%2];"
                 : "=r"(r[0]), "=r"(r[1]) : "r"(a));
}
__device__ __forceinline__ void mma16816(float* c, const uint32_t* a, const uint32_t* b) {
    asm volatile("mma.sync.aligned.m16n8k16.row.col.f32.f16.f16.f32 "
                 "{%0,%1,%2,%3}, {%4,%5,%6,%7}, {%8,%9}, {%0,%1,%2,%3};"
                 : "+f"(c[0]), "+f"(c[1]), "+f"(c[2]), "+f"(c[3])
                 : "r"(a[0]), "r"(a[1]), "r"(a[2]), "r"(a[3]), "r"(b[0]), "r"(b[1]));
}

// ---------------- prep: sq norms (pad=1e30) + argmax labels ----------------
__global__ void prep_kernel(const float* __restrict__ feats,
                            const float* __restrict__ outs) {
    int n = blockIdx.x * blockDim.x + threadIdx.x;
    if (n >= N_PAD) return;
    if (n >= N_PTS) { g_sq[n] = 1e30f; return; }
    float s = 0.f;
#pragma unroll 8
    for (int c = 0; c < C_DIM; c++) {
        float v = feats[(size_t)c * N_PTS + n];
        s = fmaf(v, v, s);
    }
    g_sq[n] = s;
    float best = outs[n];
    int bl = 0;
#pragma unroll
    for (int c = 1; c < NCLS; c++) {
        float v = outs[(size_t)c * N_PTS + n];
        if (v > best) { best = v; bl = c; }
    }
    g_label[n] = bl;
}

// ---------------- transpose + fp16 hi/lo split ------------------------------
__global__ void split_kernel(const float* __restrict__ feats) {
    __shared__ float t[32][33];
    int n0 = blockIdx.x * 32, c0 = blockIdx.y * 32;
    int n = n0 + threadIdx.x;
    t[threadIdx.y][threadIdx.x] = (n < N_PTS) ? feats[(size_t)(c0 + threadIdx.y) * N_PTS + n] : 0.f;
    __syncthreads();
    int np = n0 + threadIdx.y, cp = c0 + threadIdx.x;
    float x = t[threadIdx.x][threadIdx.y];
    __half hi = __float2half_rn(x);
    __half lo = __float2half_rn(x - __half2float(hi));
    size_t o = (size_t)np * C_DIM + cp;
    g_hi[o] = hi; g_lo[o] = lo;
}

// ---------------- chunk prefetch (cp.async, SW128 swizzled) -----------------
__device__ __forceinline__ void prefetch_chunk(uint32_t sb, int stage,
                                               int q0, int j0, int kc, int tid) {
    uint32_t st = sb + stage * STAGE_BYTES;
    // A: 2 planes x 256 rows x 8 x 16B
#pragma unroll
    for (int i = 0; i < 8; i++) {
        int t = tid + i * NTH;
        int plane = t >> 11, rem = t & 2047;
        int row = rem >> 3, u = rem & 7;
        const __half* src = (plane ? g_lo : g_hi) + (size_t)(q0 + row) * C_DIM + kc * KC + u * 8;
        uint32_t dst = st + plane * 32768 + row * 128 + ((u ^ (row & 7)) << 4);
        cp_async16(dst, src);
    }
    // B: 2 planes x 128 rows x 8 x 16B
#pragma unroll
    for (int i = 0; i < 4; i++) {
        int t = tid + i * NTH;
        int plane = t >> 10, rem = t & 1023;
        int row = rem >> 3, u = rem & 7;
        const __half* src = (plane ? g_lo : g_hi) + (size_t)(j0 + row) * C_DIM + kc * KC + u * 8;
        uint32_t dst = st + 65536 + plane * 16384 + row * 128 + ((u ^ (row & 7)) << 4);
        cp_async16(dst, src);
    }
    cp_commit();
}

// ---------------- fused mma.sync GEMM + top-9 + entropy ---------------------
__global__ __launch_bounds__(NTH, 1)
void gemm_knn_kernel(float* __restrict__ out) {
    extern __shared__ char smraw[];
    uint32_t sbr = smem_u32(smraw);
    uint32_t sb = (sbr + 1023u) & ~1023u;
    char* smem = smraw + (sb - sbr);

    const int tid = threadIdx.x;
    const int l = tid & 31, w = tid >> 5;
    const int wm = w >> 2, wn = w & 3;           // warp grid 4x4
    const int q0 = blockIdx.x * MT;

    // per-lane ldmatrix address components
    const int lrA = l & 15;            // A row within m16
    const int luA = l >> 4;            // A k-unit add
    const int lrB = l & 7;             // B row within n8
    const int luB = (l >> 3) & 1;      // B k-unit add

    float* kdp = (float*)(smem + SM_TOP) + tid * 12;
    int*   kip = (int*)(smem + SM_TOP + 12288) + tid * 12;
    float sqq = 0.f, kmax = INFINITY;
    int kpos = 0;
    if (tid < MT) {
        sqq = g_sq[q0 + tid];
#pragma unroll
        for (int t = 0; t < KNN; t++) { kdp[t] = INFINITY; kip[t] = 0; }
    }

    float* ds = (float*)smem;                      // dist_s[n][q], overlaps stages
    float* sqc = (float*)(smem + SM_SQC);

    for (int jt = 0; jt < NJT; jt++) {
        const int j0 = jt * NT;
        if (tid < NT) sqc[tid] = g_sq[j0 + tid];

        float acc[4][4][4];
#pragma unroll
        for (int mb = 0; mb < 4; mb++)
#pragma unroll
            for (int nb = 0; nb < 4; nb++)
#pragma unroll
                for (int r = 0; r < 4; r++) acc[mb][nb][r] = 0.f;

        prefetch_chunk(sb, 0, q0, j0, 0, tid);

        for (int kc = 0; kc < NCHUNK; kc++) {
            if (kc + 1 < NCHUNK) {
                prefetch_chunk(sb, (kc + 1) & 1, q0, j0, kc + 1, tid);
                asm volatile("cp.async.wait_group 1;" ::: "memory");
            } else {
                asm volatile("cp.async.wait_group 0;" ::: "memory");
            }
            __syncthreads();

            uint32_t stg = sb + (kc & 1) * STAGE_BYTES;
#pragma unroll
            for (int p = 0; p < 3; p++) {          // hh, hl, lh
                uint32_t ab = stg + ((p == 2) ? 32768 : 0);
                uint32_t bb = stg + 65536 + ((p == 1) ? 16384 : 0);
#pragma unroll
                for (int k16 = 0; k16 < 4; k16++) {
                    int u = k16 * 2;
                    uint32_t a[4][4], b[4][2];
#pragma unroll
                    for (int mb = 0; mb < 4; mb++) {
                        int row = wm * 64 + mb * 16 + lrA;
                        uint32_t ad = ab + row * 128 + (((u + luA) ^ (row & 7)) << 4);
                        ldsm_x4(a[mb], ad);
                    }
#pragma unroll
                    for (int nb = 0; nb < 4; nb++) {
                        int rowb = wn * 32 + nb * 8 + lrB;
                        uint32_t bd = bb + rowb * 128 + (((u + luB) ^ (rowb & 7)) << 4);
                        ldsm_x2(b[nb], bd);
                    }
#pragma unroll
                    for (int mb = 0; mb < 4; mb++)
#pragma unroll
                        for (int nb = 0; nb < 4; nb++)
                            mma16816(acc[mb][nb], a[mb], b[nb]);
                }
            }
            __syncthreads();
        }

        // ---- epilogue: dump dots transposed, scan top-9 ----
#pragma unroll
        for (int mb = 0; mb < 4; mb++)
#pragma unroll
            for (int nb = 0; nb < 4; nb++) {
                int q = wm * 64 + mb * 16 + (l >> 2);
                int n = wn * 32 + nb * 8 + (l & 3) * 2;
                ds[(size_t)n * DSTRIDE + q]           = acc[mb][nb][0];
                ds[(size_t)(n + 1) * DSTRIDE + q]     = acc[mb][nb][1];
                ds[(size_t)n * DSTRIDE + q + 8]       = acc[mb][nb][2];
                ds[(size_t)(n + 1) * DSTRIDE + q + 8] = acc[mb][nb][3];
            }
        __syncthreads();

        if (tid < MT) {
            for (int n = 0; n < NT; n++) {
                float d = sqq + sqc[n] - 2.f * ds[(size_t)n * DSTRIDE + tid];
                if (d < kmax) {
                    kdp[kpos] = d;
                    kip[kpos] = j0 + n;
                    kmax = kdp[0]; kpos = 0;
#pragma unroll
                    for (int t = 1; t < KNN; t++)
                        if (kdp[t] > kmax) { kmax = kdp[t]; kpos = t; }
                }
            }
        }
        __syncthreads();
    }

    // ---- entropy of 9 neighbor labels ----
    if (tid < MT) {
        int q = q0 + tid;
        if (q < N_PTS) {
            int cnt[NCLS];
#pragma unroll
            for (int c = 0; c < NCLS; c++) cnt[c] = 0;
#pragma unroll
            for (int t = 0; t < KNN; t++) cnt[g_label[kip[t]]]++;
            float s = 0.f;
#pragma unroll
            for (int c = 0; c < NCLS; c++) {
                if (cnt[c] > 0) {
                    float p = (float)cnt[c] * (1.f / 9.f);
                    s -= p * logf(p + 1e-6f);
                }
            }
            out[q] = s * (1.f / logf(19.f));
        }
    }
}

// ---------------- launch ----------------------------------------------------
extern "C" void kernel_launch(void* const* d_in, const int* in_sizes, int n_in,
                              void* d_out, int out_size) {
    const float* feats = (const float*)d_in[0];  // [512, 32400]
    const float* outs  = (const float*)d_in[1];  // [19, 32400]
    float* out = (float*)d_out;

    cudaFuncSetAttribute(gemm_knn_kernel,
                         cudaFuncAttributeMaxDynamicSharedMemorySize, DYNSMEM);

    cudaMemsetAsync(out, 0, (size_t)out_size * sizeof(float), 0);
    prep_kernel<<<(N_PAD + 255) / 256, 256>>>(feats, outs);
    {
        dim3 g(N_PAD / 32, C_DIM / 32), b(32, 32);
        split_kernel<<<g, b>>>(feats);
    }
    gemm_knn_kernel<<<NCTAS, NTH, DYNSMEM>>>(out);
}

// round 4
// speedup vs baseline: 2.6661x; 1.7832x over previous
#include <cuda_runtime.h>
#include <cuda_fp16.h>
#include <math.h>
#include <stdint.h>

#define N_PTS  32400
#define NSTRIP 127
#define SLEN   256
#define N_PAD  (NSTRIP * SLEN)   // 32512
#define C_DIM  512
#define NCLS   19
#define KNN    9
#define NSLOT  63                // foreign contributions per strip

#define MT 256                   // rows (queries) per CTA tile
#define NT 128                   // cols (candidates) per half-tile
#define KC 64                    // fp16 per K chunk (128B rows)
#define NCHUNK (C_DIM / KC)      // 8
#define NTH 512
#define NUNITS 128               // 64 strip-pairs x 2 N-halves

// smem: stage = A(2 planes x 256 x 128B) + B(2 x 128 x 128B)
#define STAGE_BYTES 98304
#define SM_TOP   (2 * STAGE_BYTES)      // 196608
#define SM_KD    SM_TOP                 // 256*12 floats
#define SM_KI    (SM_TOP + 12288)
#define SM_SQC   (SM_TOP + 24576)       // 128 floats
#define SM_SQR   (SM_SQC + 512)         // 256 floats
#define DYNSMEM  (SM_SQR + 1024 + 1024)
#define DSTRIDE  261                    // dist_s row stride (conflict-free both scans)

// ---------------- device globals ----------------
__device__ __half g_hi[(size_t)N_PAD * C_DIM];
__device__ __half g_lo[(size_t)N_PAD * C_DIM];
__device__ float  g_sq[N_PAD];
__device__ int    g_label[N_PTS];
// column-partial top-9: [strip][slot][t][col]  (coalesced in col)
__device__ float  g_part_d[(size_t)NSTRIP * NSLOT * KNN * SLEN];
__device__ int    g_part_i[(size_t)NSTRIP * NSLOT * KNN * SLEN];
// local row top-9 at end of kernel1: [strip][t][q]
__device__ float  g_loc_d[(size_t)NSTRIP * KNN * SLEN];
__device__ int    g_loc_i[(size_t)NSTRIP * KNN * SLEN];

// ---------------- helpers ----------------
__device__ __forceinline__ uint32_t smem_u32(const void* p) {
    uint32_t a;
    asm("{ .reg .u64 t; cvta.to.shared.u64 t, %1; cvt.u32.u64 %0, t; }" : "=r"(a) : "l"(p));
    return a;
}
__device__ __forceinline__ void cp_async16(uint32_t dst, const void* src) {
    asm volatile("cp.async.cg.shared.global [%0], [%1], 16;"
                 :: "r"(dst), "l"(__cvta_generic_to_global(src)) : "memory");
}
__device__ __forceinline__ void ldsm_x4(uint32_t* r, uint32_t a) {
    asm volatile("ldmatrix.sync.aligned.m8n8.x4.shared.b16 {%0,%1,%2,%3}, [%4];"
                 : "=r"(r[0]), "=r"(r[1]), "=r"(r[2]), "=r"(r[3]) : "r"(a));
}
__device__ __forceinline__ void mma16816(float* c, const uint32_t* a, const uint32_t* b) {
    asm volatile("mma.sync.aligned.m16n8k16.row.col.f32.f16.f16.f32 "
                 "{%0,%1,%2,%3}, {%4,%5,%6,%7}, {%8,%9}, {%0,%1,%2,%3};"
                 : "+f"(c[0]), "+f"(c[1]), "+f"(c[2]), "+f"(c[3])
                 : "r"(a[0]), "r"(a[1]), "r"(a[2]), "r"(a[3]), "r"(b[0]), "r"(b[1]));
}

// ---------------- prep: sq norms (pad=1e30) + argmax labels ----------------
__global__ void prep_kernel(const float* __restrict__ feats,
                            const float* __restrict__ outs) {
    int n = blockIdx.x * blockDim.x + threadIdx.x;
    if (n >= N_PAD) return;
    if (n >= N_PTS) { g_sq[n] = 1e30f; return; }
    float s = 0.f;
#pragma unroll 8
    for (int c = 0; c < C_DIM; c++) {
        float v = feats[(size_t)c * N_PTS + n];
        s = fmaf(v, v, s);
    }
    g_sq[n] = s;
    float best = outs[n];
    int bl = 0;
#pragma unroll
    for (int c = 1; c < NCLS; c++) {
        float v = outs[(size_t)c * N_PTS + n];
        if (v > best) { best = v; bl = c; }
    }
    g_label[n] = bl;
}

// ---------------- transpose + fp16 hi/lo split ------------------------------
__global__ void split_kernel(const float* __restrict__ feats) {
    __shared__ float t[32][33];
    int n0 = blockIdx.x * 32, c0 = blockIdx.y * 32;
    int n = n0 + threadIdx.x;
    t[threadIdx.y][threadIdx.x] = (n < N_PTS) ? feats[(size_t)(c0 + threadIdx.y) * N_PTS + n] : 0.f;
    __syncthreads();
    int np = n0 + threadIdx.y, cp = c0 + threadIdx.x;
    float x = t[threadIdx.x][threadIdx.y];
    __half hi = __float2half_rn(x);
    __half lo = __float2half_rn(x - __half2float(hi));
    size_t o = (size_t)np * C_DIM + cp;
    g_hi[o] = hi; g_lo[o] = lo;
}

// ---------------- chunk prefetch (cp.async, SW128 swizzled) -----------------
__device__ __forceinline__ void prefetch_chunk(uint32_t sb, int stage,
                                               int q0, int j0, int kc, int tid) {
    uint32_t st = sb + stage * STAGE_BYTES;
#pragma unroll
    for (int i = 0; i < 8; i++) {   // A: 2 planes x 256 rows x 8 x 16B
        int t = tid + i * NTH;
        int plane = t >> 11, rem = t & 2047;
        int row = rem >> 3, u = rem & 7;
        const __half* src = (plane ? g_lo : g_hi) + (size_t)(q0 + row) * C_DIM + kc * KC + u * 8;
        cp_async16(st + plane * 32768 + row * 128 + ((u ^ (row & 7)) << 4), src);
    }
#pragma unroll
    for (int i = 0; i < 4; i++) {   // B: 2 planes x 128 rows x 8 x 16B
        int t = tid + i * NTH;
        int plane = t >> 10, rem = t & 1023;
        int row = rem >> 3, u = rem & 7;
        const __half* src = (plane ? g_lo : g_hi) + (size_t)(j0 + row) * C_DIM + kc * KC + u * 8;
        cp_async16(st + 65536 + plane * 16384 + row * 128 + ((u ^ (row & 7)) << 4), src);
    }
    asm volatile("cp.async.commit_group;" ::: "memory");
}

// ---------------- symmetric GEMM + bidirectional top-9 ----------------------
__global__ __launch_bounds__(NTH, 1)
void gemm_knn_kernel() {
    extern __shared__ char smraw[];
    uint32_t sbr = smem_u32(smraw);
    uint32_t sb = (sbr + 1023u) & ~1023u;
    char* smem = smraw + (sb - sbr);

    const int tid = threadIdx.x;
    const int l = tid & 31, w = tid >> 5;
    const int wm = w >> 2, wn = w & 3;        // warp grid 4x4 (64x32 warp tile)
    const int istrip = blockIdx.x;
    const int q0 = istrip * SLEN;

    const int lrA = l & 15, luA = l >> 4;

    float* kdp = (float*)(smem + SM_KD) + tid * 12;
    int*   kip = (int*)(smem + SM_KI) + tid * 12;
    float* sqc = (float*)(smem + SM_SQC);
    float* sqr = (float*)(smem + SM_SQR);
    float* ds  = (float*)smem;                // overlaps stage buffers

    float sqq = 0.f, kmax = INFINITY;
    int kpos = 0;
    if (tid < MT) {
        sqq = g_sq[q0 + tid];
        sqr[tid] = sqq;
#pragma unroll
        for (int t = 0; t < KNN; t++) { kdp[t] = INFINITY; kip[t] = 0; }
    }
    __syncthreads();

    for (int unit = 0; unit < NUNITS; unit++) {
        const int d = unit >> 1, h = unit & 1;
        const int jstrip = (istrip + d) % NSTRIP;
        const int j0 = jstrip * SLEN + h * NT;
        if (tid < NT) sqc[tid] = g_sq[j0 + tid];

        float acc[4][4][4];
#pragma unroll
        for (int mb = 0; mb < 4; mb++)
#pragma unroll
            for (int nb = 0; nb < 4; nb++)
#pragma unroll
                for (int r = 0; r < 4; r++) acc[mb][nb][r] = 0.f;

        prefetch_chunk(sb, 0, q0, j0, 0, tid);

        for (int kc = 0; kc < NCHUNK; kc++) {
            if (kc + 1 < NCHUNK) {
                prefetch_chunk(sb, (kc + 1) & 1, q0, j0, kc + 1, tid);
                asm volatile("cp.async.wait_group 1;" ::: "memory");
            } else {
                asm volatile("cp.async.wait_group 0;" ::: "memory");
            }
            __syncthreads();

            uint32_t stg = sb + (kc & 1) * STAGE_BYTES;
#pragma unroll
            for (int p = 0; p < 3; p++) {     // hh, hl, lh
                uint32_t ab = stg + ((p == 2) ? 32768 : 0);
                uint32_t bb = stg + 65536 + ((p == 1) ? 16384 : 0);
#pragma unroll
                for (int k16 = 0; k16 < 4; k16++) {
                    int u = k16 * 2;
                    uint32_t a[4][4], b[4][2];
#pragma unroll
                    for (int mb = 0; mb < 4; mb++) {
                        int row = wm * 64 + mb * 16 + lrA;
                        ldsm_x4(a[mb], ab + row * 128 + (((u + luA) ^ (row & 7)) << 4));
                    }
#pragma unroll
                    for (int nbp = 0; nbp < 2; nbp++) {
                        int rowb = wn * 32 + (nbp * 2 + (l >> 4)) * 8 + (l & 7);
                        int ku = u + ((l >> 3) & 1);
                        uint32_t tmp[4];
                        ldsm_x4(tmp, bb + rowb * 128 + ((ku ^ (rowb & 7)) << 4));
                        b[nbp * 2][0] = tmp[0]; b[nbp * 2][1] = tmp[1];
                        b[nbp * 2 + 1][0] = tmp[2]; b[nbp * 2 + 1][1] = tmp[3];
                    }
#pragma unroll
                    for (int mb = 0; mb < 4; mb++)
#pragma unroll
                        for (int nb = 0; nb < 4; nb++)
                            mma16816(acc[mb][nb], a[mb], b[nb]);
                }
            }
            __syncthreads();
        }

        // ---- dump dots transposed: ds[n][q] ----
#pragma unroll
        for (int mb = 0; mb < 4; mb++)
#pragma unroll
            for (int nb = 0; nb < 4; nb++) {
                int q = wm * 64 + mb * 16 + (l >> 2);
                int n = wn * 32 + nb * 8 + (l & 3) * 2;
                ds[(size_t)n * DSTRIDE + q]           = acc[mb][nb][0];
                ds[(size_t)(n + 1) * DSTRIDE + q]     = acc[mb][nb][1];
                ds[(size_t)n * DSTRIDE + q + 8]       = acc[mb][nb][2];
                ds[(size_t)(n + 1) * DSTRIDE + q + 8] = acc[mb][nb][3];
            }
        __syncthreads();

        // ---- row scan: running top-9 for own queries ----
        if (tid < MT) {
            for (int n = 0; n < NT; n++) {
                float dd = sqq + sqc[n] - 2.f * ds[(size_t)n * DSTRIDE + tid];
                if (dd < kmax) {
                    kdp[kpos] = dd;
                    kip[kpos] = j0 + n;
                    kmax = kdp[0]; kpos = 0;
#pragma unroll
                    for (int t = 1; t < KNN; t++)
                        if (kdp[t] > kmax) { kmax = kdp[t]; kpos = t; }
                }
            }
        } else if (tid < MT + NT && d > 0) {
            // ---- column scan: fresh top-9 over this tile's 256 rows ----
            int c = tid - MT;
            float sc = sqc[c];
            float ckd[KNN]; int cki[KNN];
#pragma unroll
            for (int t = 0; t < KNN; t++) { ckd[t] = INFINITY; cki[t] = 0; }
            float cmax = INFINITY; int cpos = 0;
            for (int q = 0; q < MT; q++) {
                float dd = sc + sqr[q] - 2.f * ds[(size_t)c * DSTRIDE + q];
                if (dd < cmax) {
                    ckd[cpos] = dd;
                    cki[cpos] = q0 + q;
                    cmax = ckd[0]; cpos = 0;
#pragma unroll
                    for (int t = 1; t < KNN; t++)
                        if (ckd[t] > cmax) { cmax = ckd[t]; cpos = t; }
                }
            }
            size_t base = (((size_t)jstrip * NSLOT + (d - 1)) * KNN) * SLEN + h * NT + c;
#pragma unroll
            for (int t = 0; t < KNN; t++) {
                g_part_d[base + (size_t)t * SLEN] = ckd[t];
                g_part_i[base + (size_t)t * SLEN] = cki[t];
            }
        }
        __syncthreads();
    }

    // ---- publish local row top-9 ----
    if (tid < MT) {
        size_t base = (size_t)istrip * KNN * SLEN + tid;
#pragma unroll
        for (int t = 0; t < KNN; t++) {
            g_loc_d[base + (size_t)t * SLEN] = kdp[t];
            g_loc_i[base + (size_t)t * SLEN] = kip[t];
        }
    }
}

// ---------------- merge partials + entropy ----------------------------------
__global__ void merge_kernel(float* __restrict__ out) {
    const int strip = blockIdx.x;
    const int tid = threadIdx.x;          // query within strip
    const int q = strip * SLEN + tid;

    float kd[KNN]; int ki[KNN];
    size_t lb = (size_t)strip * KNN * SLEN + tid;
#pragma unroll
    for (int t = 0; t < KNN; t++) {
        kd[t] = g_loc_d[lb + (size_t)t * SLEN];
        ki[t] = g_loc_i[lb + (size_t)t * SLEN];
    }
    float kmax = kd[0]; int kpos = 0;
#pragma unroll
    for (int t = 1; t < KNN; t++)
        if (kd[t] > kmax) { kmax = kd[t]; kpos = t; }

    for (int s = 0; s < NSLOT; s++) {
        size_t base = (((size_t)strip * NSLOT + s) * KNN) * SLEN + tid;
#pragma unroll
        for (int t = 0; t < KNN; t++) {
            float dd = g_part_d[base + (size_t)t * SLEN];
            if (dd < kmax) {
                int ii = g_part_i[base + (size_t)t * SLEN];
                kd[kpos] = dd; ki[kpos] = ii;
                kmax = kd[0]; kpos = 0;
#pragma unroll
                for (int t2 = 1; t2 < KNN; t2++)
                    if (kd[t2] > kmax) { kmax = kd[t2]; kpos = t2; }
            }
        }
    }

    if (q < N_PTS) {
        int cnt[NCLS];
#pragma unroll
        for (int c = 0; c < NCLS; c++) cnt[c] = 0;
#pragma unroll
        for (int t = 0; t < KNN; t++) cnt[g_label[ki[t]]]++;
        float s = 0.f;
#pragma unroll
        for (int c = 0; c < NCLS; c++) {
            if (cnt[c] > 0) {
                float p = (float)cnt[c] * (1.f / 9.f);
                s -= p * logf(p + 1e-6f);
            }
        }
        out[q] = s * (1.f / logf(19.f));
    }
}

// ---------------- launch ----------------------------------------------------
extern "C" void kernel_launch(void* const* d_in, const int* in_sizes, int n_in,
                              void* d_out, int out_size) {
    const float* feats = (const float*)d_in[0];  // [512, 32400]
    const float* outs  = (const float*)d_in[1];  // [19, 32400]
    float* out = (float*)d_out;

    cudaFuncSetAttribute(gemm_knn_kernel,
                         cudaFuncAttributeMaxDynamicSharedMemorySize, DYNSMEM);

    cudaMemsetAsync(out, 0, (size_t)out_size * sizeof(float), 0);
    prep_kernel<<<(N_PAD + 255) / 256, 256>>>(feats, outs);
    {
        dim3 g(N_PAD / 32, C_DIM / 32), b(32, 32);
        split_kernel<<<g, b>>>(feats);
    }
    gemm_knn_kernel<<<NSTRIP, NTH, DYNSMEM>>>();
    merge_kernel<<<NSTRIP, SLEN>>>(out);
}

// round 5
// speedup vs baseline: 3.8183x; 1.4322x over previous
#include <cuda_runtime.h>
#include <cuda_fp16.h>
#include <math.h>
#include <stdint.h>

#define N_PTS  32400
#define NSTRIP 127
#define SLEN   256
#define N_PAD  (NSTRIP * SLEN)   // 32512
#define C_DIM  512
#define NCLS   19
#define KNN    9
#define NSLOT  63
#define T_SEL  16                // pruning list size

#define MT 256
#define NT 128
#define KC 64
#define NCHUNK (C_DIM / KC)      // 8
#define NTH 512
#define NUNITS 128               // 64 strip-pairs x 2 N-halves

// phase-1 smem: hh-only stage = A 256x128B (32K) + B 128x128B (16K)
#define ST_BYTES 49152
#define SM_DS   98304            // fp16 ds[128][DSH]
#define DSH     268
#define SM_KD   167936           // 256 * 16 * 4
#define SM_KI   (SM_KD + 16384)
#define SM_SQC  (SM_KI + 16384)  // 200704
#define SM_SQR  (SM_SQC + 512)
#define DYNSMEM (SM_SQR + 1024 + 1024)

// ---------------- device globals ----------------
__device__ __half g_hi[(size_t)N_PAD * C_DIM];
__device__ __half g_lo[(size_t)N_PAD * C_DIM];
__device__ float  g_sq[N_PAD];
__device__ int    g_label[N_PTS];
// column partial top-16 (approx): [strip][slot][t][col]
__device__ float  g_part_d[(size_t)NSTRIP * NSLOT * T_SEL * SLEN];
__device__ int    g_part_i[(size_t)NSTRIP * NSLOT * T_SEL * SLEN];
// local row top-16: [strip][t][q]
__device__ float  g_loc_d[(size_t)NSTRIP * T_SEL * SLEN];
__device__ int    g_loc_i[(size_t)NSTRIP * T_SEL * SLEN];
// merged candidate indices: [q][16]
__device__ int    g_mrg_i[(size_t)N_PAD * T_SEL];

// ---------------- helpers ----------------
__device__ __forceinline__ uint32_t smem_u32(const void* p) {
    uint32_t a;
    asm("{ .reg .u64 t; cvta.to.shared.u64 t, %1; cvt.u32.u64 %0, t; }" : "=r"(a) : "l"(p));
    return a;
}
__device__ __forceinline__ void cp_async16(uint32_t dst, const void* src) {
    asm volatile("cp.async.cg.shared.global [%0], [%1], 16;"
                 :: "r"(dst), "l"(__cvta_generic_to_global(src)) : "memory");
}
__device__ __forceinline__ void ldsm_x4(uint32_t* r, uint32_t a) {
    asm volatile("ldmatrix.sync.aligned.m8n8.x4.shared.b16 {%0,%1,%2,%3}, [%4];"
                 : "=r"(r[0]), "=r"(r[1]), "=r"(r[2]), "=r"(r[3]) : "r"(a));
}
__device__ __forceinline__ void mma16816(float* c, const uint32_t* a, const uint32_t* b) {
    asm volatile("mma.sync.aligned.m16n8k16.row.col.f32.f16.f16.f32 "
                 "{%0,%1,%2,%3}, {%4,%5,%6,%7}, {%8,%9}, {%0,%1,%2,%3};"
                 : "+f"(c[0]), "+f"(c[1]), "+f"(c[2]), "+f"(c[3])
                 : "r"(a[0]), "r"(a[1]), "r"(a[2]), "r"(a[3]), "r"(b[0]), "r"(b[1]));
}

// ---------------- prep: sq norms (pad=1e30) + argmax labels ----------------
__global__ void prep_kernel(const float* __restrict__ feats,
                            const float* __restrict__ outs) {
    int n = blockIdx.x * blockDim.x + threadIdx.x;
    if (n >= N_PAD) return;
    if (n >= N_PTS) { g_sq[n] = 1e30f; return; }
    float s = 0.f;
#pragma unroll 8
    for (int c = 0; c < C_DIM; c++) {
        float v = feats[(size_t)c * N_PTS + n];
        s = fmaf(v, v, s);
    }
    g_sq[n] = s;
    float best = outs[n];
    int bl = 0;
#pragma unroll
    for (int c = 1; c < NCLS; c++) {
        float v = outs[(size_t)c * N_PTS + n];
        if (v > best) { best = v; bl = c; }
    }
    g_label[n] = bl;
}

// ---------------- transpose + fp16 hi/lo split ------------------------------
__global__ void split_kernel(const float* __restrict__ feats) {
    __shared__ float t[32][33];
    int n0 = blockIdx.x * 32, c0 = blockIdx.y * 32;
    int n = n0 + threadIdx.x;
    t[threadIdx.y][threadIdx.x] = (n < N_PTS) ? feats[(size_t)(c0 + threadIdx.y) * N_PTS + n] : 0.f;
    __syncthreads();
    int np = n0 + threadIdx.y, cp = c0 + threadIdx.x;
    float x = t[threadIdx.x][threadIdx.y];
    __half hi = __float2half_rn(x);
    __half lo = __float2half_rn(x - __half2float(hi));
    size_t o = (size_t)np * C_DIM + cp;
    g_hi[o] = hi; g_lo[o] = lo;
}

// ---------------- hh chunk prefetch ----------------------------------------
__device__ __forceinline__ void prefetch_chunk(uint32_t sb, int stage,
                                               int q0, int j0, int kc, int tid) {
    uint32_t st = sb + stage * ST_BYTES;
#pragma unroll
    for (int i = 0; i < 4; i++) {   // A: 256 rows x 8 x 16B
        int t = tid + i * NTH;
        int row = t >> 3, u = t & 7;
        const __half* src = g_hi + (size_t)(q0 + row) * C_DIM + kc * KC + u * 8;
        cp_async16(st + row * 128 + ((u ^ (row & 7)) << 4), src);
    }
#pragma unroll
    for (int i = 0; i < 2; i++) {   // B: 128 rows x 8 x 16B
        int t = tid + i * NTH;
        int row = t >> 3, u = t & 7;
        const __half* src = g_hi + (size_t)(j0 + row) * C_DIM + kc * KC + u * 8;
        cp_async16(st + 32768 + row * 128 + ((u ^ (row & 7)) << 4), src);
    }
    asm volatile("cp.async.commit_group;" ::: "memory");
}

// ---------------- phase 1: hh GEMM + bidirectional top-16 -------------------
__global__ __launch_bounds__(NTH, 1)
void phase1_kernel() {
    extern __shared__ char smraw[];
    uint32_t sbr = smem_u32(smraw);
    uint32_t sb = (sbr + 1023u) & ~1023u;
    char* smem = smraw + (sb - sbr);

    const int tid = threadIdx.x;
    const int l = tid & 31, w = tid >> 5;
    const int wm = w >> 2, wn = w & 3;
    const int istrip = blockIdx.x;
    const int q0 = istrip * SLEN;
    const int lrA = l & 15, luA = l >> 4;

    float* kdp = (float*)(smem + SM_KD) + tid * T_SEL;
    int*   kip = (int*)(smem + SM_KI) + tid * T_SEL;
    float* sqc = (float*)(smem + SM_SQC);
    float* sqr = (float*)(smem + SM_SQR);
    __half* dsh = (__half*)(smem + SM_DS);

    float sqq = 0.f, kmax = INFINITY;
    int kpos = 0;
    if (tid < MT) {
        sqq = g_sq[q0 + tid];
        sqr[tid] = sqq;
#pragma unroll
        for (int t = 0; t < T_SEL; t++) { kdp[t] = INFINITY; kip[t] = 0; }
    }
    __syncthreads();

    prefetch_chunk(sb, 0, q0, q0, 0, tid);

    for (int unit = 0; unit < NUNITS; unit++) {
        const int d = unit >> 1, h = unit & 1;
        const int jstrip = (istrip + d) % NSTRIP;
        const int j0 = jstrip * SLEN + h * NT;
        if (tid < NT) sqc[tid] = g_sq[j0 + tid];

        float acc[4][4][4];
#pragma unroll
        for (int mb = 0; mb < 4; mb++)
#pragma unroll
            for (int nb = 0; nb < 4; nb++)
#pragma unroll
                for (int r = 0; r < 4; r++) acc[mb][nb][r] = 0.f;

        for (int kc = 0; kc < NCHUNK; kc++) {
            if (kc + 1 < NCHUNK) {
                prefetch_chunk(sb, (kc + 1) & 1, q0, j0, kc + 1, tid);
                asm volatile("cp.async.wait_group 1;" ::: "memory");
            } else if (unit + 1 < NUNITS) {
                // prefetch next unit's chunk 0 into stage 0 (overlaps epilogue)
                int dn = (unit + 1) >> 1, hn = (unit + 1) & 1;
                int j0n = ((istrip + dn) % NSTRIP) * SLEN + hn * NT;
                prefetch_chunk(sb, 0, q0, j0n, 0, tid);
                asm volatile("cp.async.wait_group 1;" ::: "memory");
            } else {
                asm volatile("cp.async.wait_group 0;" ::: "memory");
            }
            __syncthreads();

            uint32_t stg = sb + (kc & 1) * ST_BYTES;
            uint32_t ab = stg, bb = stg + 32768;
#pragma unroll
            for (int k16 = 0; k16 < 4; k16++) {
                int u = k16 * 2;
                uint32_t a[4][4], b[4][2];
#pragma unroll
                for (int mb = 0; mb < 4; mb++) {
                    int row = wm * 64 + mb * 16 + lrA;
                    ldsm_x4(a[mb], ab + row * 128 + (((u + luA) ^ (row & 7)) << 4));
                }
#pragma unroll
                for (int nbp = 0; nbp < 2; nbp++) {
                    int rowb = wn * 32 + (nbp * 2 + (l >> 4)) * 8 + (l & 7);
                    int ku = u + ((l >> 3) & 1);
                    uint32_t tmp[4];
                    ldsm_x4(tmp, bb + rowb * 128 + ((ku ^ (rowb & 7)) << 4));
                    b[nbp * 2][0] = tmp[0]; b[nbp * 2][1] = tmp[1];
                    b[nbp * 2 + 1][0] = tmp[2]; b[nbp * 2 + 1][1] = tmp[3];
                }
#pragma unroll
                for (int mb = 0; mb < 4; mb++)
#pragma unroll
                    for (int nb = 0; nb < 4; nb++)
                        mma16816(acc[mb][nb], a[mb], b[nb]);
            }
            __syncthreads();
        }

        // ---- dump dots (fp16) transposed: dsh[n][q] ----
#pragma unroll
        for (int mb = 0; mb < 4; mb++)
#pragma unroll
            for (int nb = 0; nb < 4; nb++) {
                int q = wm * 64 + mb * 16 + (l >> 2);
                int n = wn * 32 + nb * 8 + (l & 3) * 2;
                dsh[(size_t)n * DSH + q]           = __float2half_rn(acc[mb][nb][0]);
                dsh[(size_t)(n + 1) * DSH + q]     = __float2half_rn(acc[mb][nb][1]);
                dsh[(size_t)n * DSH + q + 8]       = __float2half_rn(acc[mb][nb][2]);
                dsh[(size_t)(n + 1) * DSH + q + 8] = __float2half_rn(acc[mb][nb][3]);
            }
        __syncthreads();

        // ---- row scan: running top-16 for own queries ----
        if (tid < MT) {
            for (int n = 0; n < NT; n++) {
                float dd = sqq + sqc[n] - 2.f * __half2float(dsh[(size_t)n * DSH + tid]);
                if (dd < kmax) {
                    kdp[kpos] = dd;
                    kip[kpos] = j0 + n;
                    kmax = kdp[0]; kpos = 0;
#pragma unroll
                    for (int t = 1; t < T_SEL; t++)
                        if (kdp[t] > kmax) { kmax = kdp[t]; kpos = t; }
                }
            }
        } else if (tid < MT + NT && d > 0) {
            // ---- column scan: fresh top-16 over 256 rows ----
            int c = tid - MT;
            float sc = sqc[c];
            float ckd[T_SEL]; int cki[T_SEL];
#pragma unroll
            for (int t = 0; t < T_SEL; t++) { ckd[t] = INFINITY; cki[t] = 0; }
            float cmax = INFINITY; int cpos = 0;
            for (int q = 0; q < MT; q++) {
                float dd = sc + sqr[q] - 2.f * __half2float(dsh[(size_t)c * DSH + q]);
                if (dd < cmax) {
                    ckd[cpos] = dd;
                    cki[cpos] = q0 + q;
                    cmax = ckd[0]; cpos = 0;
#pragma unroll
                    for (int t = 1; t < T_SEL; t++)
                        if (ckd[t] > cmax) { cmax = ckd[t]; cpos = t; }
                }
            }
            size_t base = (((size_t)jstrip * NSLOT + (d - 1)) * T_SEL) * SLEN + h * NT + c;
#pragma unroll
            for (int t = 0; t < T_SEL; t++) {
                g_part_d[base + (size_t)t * SLEN] = ckd[t];
                g_part_i[base + (size_t)t * SLEN] = cki[t];
            }
        }
        __syncthreads();
    }

    if (tid < MT) {
        size_t base = (size_t)istrip * T_SEL * SLEN + tid;
#pragma unroll
        for (int t = 0; t < T_SEL; t++) {
            g_loc_d[base + (size_t)t * SLEN] = kdp[t];
            g_loc_i[base + (size_t)t * SLEN] = kip[t];
        }
    }
}

// ---------------- merge partials -> candidate set ---------------------------
__global__ void merge_kernel() {
    const int strip = blockIdx.x;
    const int tid = threadIdx.x;
    const int q = strip * SLEN + tid;

    float kd[T_SEL]; int ki[T_SEL];
    size_t lb = (size_t)strip * T_SEL * SLEN + tid;
#pragma unroll
    for (int t = 0; t < T_SEL; t++) {
        kd[t] = g_loc_d[lb + (size_t)t * SLEN];
        ki[t] = g_loc_i[lb + (size_t)t * SLEN];
    }
    float kmax = kd[0]; int kpos = 0;
#pragma unroll
    for (int t = 1; t < T_SEL; t++)
        if (kd[t] > kmax) { kmax = kd[t]; kpos = t; }

    for (int s = 0; s < NSLOT; s++) {
        size_t base = (((size_t)strip * NSLOT + s) * T_SEL) * SLEN + tid;
#pragma unroll
        for (int t = 0; t < T_SEL; t++) {
            float dd = g_part_d[base + (size_t)t * SLEN];
            if (dd < kmax) {
                int ii = g_part_i[base + (size_t)t * SLEN];
                kd[kpos] = dd; ki[kpos] = ii;
                kmax = kd[0]; kpos = 0;
#pragma unroll
                for (int t2 = 1; t2 < T_SEL; t2++)
                    if (kd[t2] > kmax) { kmax = kd[t2]; kpos = t2; }
            }
        }
    }
#pragma unroll
    for (int t = 0; t < T_SEL; t++)
        g_mrg_i[(size_t)q * T_SEL + t] = ki[t];
}

// ---------------- refine: exact fp32 distances on 16 candidates -------------
__global__ __launch_bounds__(256)
void refine_kernel(float* __restrict__ out) {
    const int warp = threadIdx.x >> 5, l = threadIdx.x & 31;
    const int q = blockIdx.x * 8 + warp;
    __shared__ float sd[8][T_SEL];
    __shared__ int   si[8][T_SEL];
    if (q >= N_PTS) return;

    const __half2* qh = (const __half2*)(g_hi + (size_t)q * C_DIM);
    const __half2* ql = (const __half2*)(g_lo + (size_t)q * C_DIM);
    float qx[16];
#pragma unroll
    for (int i = 0; i < 8; i++) {
        float2 h = __half22float2(qh[l + 32 * i]);
        float2 lo = __half22float2(ql[l + 32 * i]);
        qx[2 * i] = h.x + lo.x;
        qx[2 * i + 1] = h.y + lo.y;
    }
    float sqq = g_sq[q];

    for (int c = 0; c < T_SEL; c++) {
        int idx = g_mrg_i[(size_t)q * T_SEL + c];
        const __half2* ch = (const __half2*)(g_hi + (size_t)idx * C_DIM);
        const __half2* cl = (const __half2*)(g_lo + (size_t)idx * C_DIM);
        float acc = 0.f;
#pragma unroll
        for (int i = 0; i < 8; i++) {
            float2 h = __half22float2(ch[l + 32 * i]);
            float2 lo = __half22float2(cl[l + 32 * i]);
            acc = fmaf(qx[2 * i], h.x + lo.x, acc);
            acc = fmaf(qx[2 * i + 1], h.y + lo.y, acc);
        }
#pragma unroll
        for (int o = 16; o > 0; o >>= 1)
            acc += __shfl_xor_sync(0xFFFFFFFF, acc, o);
        if (l == 0) {
            sd[warp][c] = sqq + g_sq[idx] - 2.f * acc;
            si[warp][c] = idx;
        }
    }
    __syncwarp();

    if (l == 0) {
        float kd[KNN]; int ki[KNN];
#pragma unroll
        for (int t = 0; t < KNN; t++) { kd[t] = INFINITY; ki[t] = 0; }
        float kmax = INFINITY; int kpos = 0;
#pragma unroll
        for (int c = 0; c < T_SEL; c++) {
            float dd = sd[warp][c];
            if (dd < kmax) {
                kd[kpos] = dd; ki[kpos] = si[warp][c];
                kmax = kd[0]; kpos = 0;
#pragma unroll
                for (int t = 1; t < KNN; t++)
                    if (kd[t] > kmax) { kmax = kd[t]; kpos = t; }
            }
        }
        int cnt[NCLS];
#pragma unroll
        for (int c = 0; c < NCLS; c++) cnt[c] = 0;
#pragma unroll
        for (int t = 0; t < KNN; t++) cnt[g_label[ki[t]]]++;
        float s = 0.f;
#pragma unroll
        for (int c = 0; c < NCLS; c++) {
            if (cnt[c] > 0) {
                float p = (float)cnt[c] * (1.f / 9.f);
                s -= p * logf(p + 1e-6f);
            }
        }
        out[q] = s * (1.f / logf(19.f));
    }
}

// ---------------- launch ----------------------------------------------------
extern "C" void kernel_launch(void* const* d_in, const int* in_sizes, int n_in,
                              void* d_out, int out_size) {
    const float* feats = (const float*)d_in[0];  // [512, 32400]
    const float* outs  = (const float*)d_in[1];  // [19, 32400]
    float* out = (float*)d_out;

    cudaFuncSetAttribute(phase1_kernel,
                         cudaFuncAttributeMaxDynamicSharedMemorySize, DYNSMEM);

    cudaMemsetAsync(out, 0, (size_t)out_size * sizeof(float), 0);
    prep_kernel<<<(N_PAD + 255) / 256, 256>>>(feats, outs);
    {
        dim3 g(N_PAD / 32, C_DIM / 32), b(32, 32);
        split_kernel<<<g, b>>>(feats);
    }
    phase1_kernel<<<NSTRIP, NTH, DYNSMEM>>>();
    merge_kernel<<<NSTRIP, SLEN>>>();
    refine_kernel<<<(N_PTS + 7) / 8, 256>>>(out);
}

// round 6
// speedup vs baseline: 4.1243x; 1.0801x over previous
#include <cuda_runtime.h>
#include <cuda_fp16.h>
#include <math.h>
#include <stdint.h>

#define N_PTS  32400
#define NSTRIP 127
#define SLEN   256
#define N_PAD  (NSTRIP * SLEN)   // 32512
#define C_DIM  512
#define NCLS   19
#define KNN    9
#define NSLOT  63
#define T_SEL  16

#define MT 256
#define NT 128
#define KC 64
#define NCHUNK (C_DIM / KC)      // 8
#define NTH 512
#define NUNITS 128

// phase-1 smem
#define ST_BYTES 49152
#define SM_DS   98304            // fp16 ds[128][DSH]
#define DSH     270              // odd word count: conflict-free col scan
#define SM_KD   167936
#define SM_KI   (SM_KD + 16384)
#define SM_SQC  (SM_KI + 16384)
#define SM_SQR  (SM_SQC + 512)
#define DYNSMEM (SM_SQR + 1024 + 1024)

#define MERGE_SMEM (3 * T_SEL * SLEN * 8)   // 98304

// ---------------- device globals ----------------
__device__ __half g_hi[(size_t)N_PAD * C_DIM];
__device__ __half g_lo[(size_t)N_PAD * C_DIM];
__device__ float  g_sq[N_PAD];
__device__ int    g_label[N_PTS];
__device__ float  g_part_d[(size_t)NSTRIP * NSLOT * T_SEL * SLEN];
__device__ int    g_part_i[(size_t)NSTRIP * NSLOT * T_SEL * SLEN];
__device__ float  g_loc_d[(size_t)NSTRIP * T_SEL * SLEN];
__device__ int    g_loc_i[(size_t)NSTRIP * T_SEL * SLEN];
__device__ int    g_mrg_i[(size_t)N_PAD * T_SEL];

// ---------------- helpers ----------------
__device__ __forceinline__ uint32_t smem_u32(const void* p) {
    uint32_t a;
    asm("{ .reg .u64 t; cvta.to.shared.u64 t, %1; cvt.u32.u64 %0, t; }" : "=r"(a) : "l"(p));
    return a;
}
__device__ __forceinline__ void cp_async16(uint32_t dst, const void* src) {
    asm volatile("cp.async.cg.shared.global [%0], [%1], 16;"
                 :: "r"(dst), "l"(__cvta_generic_to_global(src)) : "memory");
}
__device__ __forceinline__ void ldsm_x4(uint32_t* r, uint32_t a) {
    asm volatile("ldmatrix.sync.aligned.m8n8.x4.shared.b16 {%0,%1,%2,%3}, [%4];"
                 : "=r"(r[0]), "=r"(r[1]), "=r"(r[2]), "=r"(r[3]) : "r"(a));
}
__device__ __forceinline__ void mma16816(float* c, const uint32_t* a, const uint32_t* b) {
    asm volatile("mma.sync.aligned.m16n8k16.row.col.f32.f16.f16.f32 "
                 "{%0,%1,%2,%3}, {%4,%5,%6,%7}, {%8,%9}, {%0,%1,%2,%3};"
                 : "+f"(c[0]), "+f"(c[1]), "+f"(c[2]), "+f"(c[3])
                 : "r"(a[0]), "r"(a[1]), "r"(a[2]), "r"(a[3]), "r"(b[0]), "r"(b[1]));
}

#define INSERT16(dd, ii, kdp, kip, kmax, kpos)                                   \
    do {                                                                         \
        (kdp)[kpos] = (dd); (kip)[kpos] = (ii);                                  \
        kmax = (kdp)[0]; kpos = 0;                                               \
        _Pragma("unroll")                                                        \
        for (int _t = 1; _t < T_SEL; _t++)                                       \
            if ((kdp)[_t] > kmax) { kmax = (kdp)[_t]; kpos = _t; }               \
    } while (0)

// ---------------- prep ----------------
__global__ void prep_kernel(const float* __restrict__ feats,
                            const float* __restrict__ outs) {
    int n = blockIdx.x * blockDim.x + threadIdx.x;
    if (n >= N_PAD) return;
    if (n >= N_PTS) { g_sq[n] = 1e30f; return; }
    float s = 0.f;
#pragma unroll 8
    for (int c = 0; c < C_DIM; c++) {
        float v = feats[(size_t)c * N_PTS + n];
        s = fmaf(v, v, s);
    }
    g_sq[n] = s;
    float best = outs[n];
    int bl = 0;
#pragma unroll
    for (int c = 1; c < NCLS; c++) {
        float v = outs[(size_t)c * N_PTS + n];
        if (v > best) { best = v; bl = c; }
    }
    g_label[n] = bl;
}

// ---------------- transpose + fp16 hi/lo split -------------------------------
__global__ void split_kernel(const float* __restrict__ feats) {
    __shared__ float t[32][33];
    int n0 = blockIdx.x * 32, c0 = blockIdx.y * 32;
    int n = n0 + threadIdx.x;
    t[threadIdx.y][threadIdx.x] = (n < N_PTS) ? feats[(size_t)(c0 + threadIdx.y) * N_PTS + n] : 0.f;
    __syncthreads();
    int np = n0 + threadIdx.y, cp = c0 + threadIdx.x;
    float x = t[threadIdx.x][threadIdx.y];
    __half hi = __float2half_rn(x);
    __half lo = __float2half_rn(x - __half2float(hi));
    size_t o = (size_t)np * C_DIM + cp;
    g_hi[o] = hi; g_lo[o] = lo;
}

// ---------------- hh chunk prefetch -----------------------------------------
__device__ __forceinline__ void prefetch_chunk(uint32_t sb, int stage,
                                               int q0, int j0, int kc, int tid) {
    uint32_t st = sb + stage * ST_BYTES;
#pragma unroll
    for (int i = 0; i < 4; i++) {
        int t = tid + i * NTH;
        int row = t >> 3, u = t & 7;
        const __half* src = g_hi + (size_t)(q0 + row) * C_DIM + kc * KC + u * 8;
        cp_async16(st + row * 128 + ((u ^ (row & 7)) << 4), src);
    }
#pragma unroll
    for (int i = 0; i < 2; i++) {
        int t = tid + i * NTH;
        int row = t >> 3, u = t & 7;
        const __half* src = g_hi + (size_t)(j0 + row) * C_DIM + kc * KC + u * 8;
        cp_async16(st + 32768 + row * 128 + ((u ^ (row & 7)) << 4), src);
    }
    asm volatile("cp.async.commit_group;" ::: "memory");
}

// ---------------- phase 1: hh GEMM + bidirectional top-16 -------------------
__global__ __launch_bounds__(NTH, 1)
void phase1_kernel() {
    extern __shared__ char smraw[];
    uint32_t sbr = smem_u32(smraw);
    uint32_t sb = (sbr + 1023u) & ~1023u;
    char* smem = smraw + (sb - sbr);

    const int tid = threadIdx.x;
    const int l = tid & 31, w = tid >> 5;
    const int wm = w >> 2, wn = w & 3;
    const int istrip = blockIdx.x;
    const int q0 = istrip * SLEN;
    const int lrA = l & 15, luA = l >> 4;

    float* kdp = (float*)(smem + SM_KD) + tid * T_SEL;
    int*   kip = (int*)(smem + SM_KI) + tid * T_SEL;
    float* sqc = (float*)(smem + SM_SQC);
    float* sqr = (float*)(smem + SM_SQR);
    __half* dsh = (__half*)(smem + SM_DS);

    float sqq = 0.f, kmax = INFINITY;
    int kpos = 0;
    if (tid < MT) {
        sqq = g_sq[q0 + tid];
        sqr[tid] = sqq;
#pragma unroll
        for (int t = 0; t < T_SEL; t++) { kdp[t] = INFINITY; kip[t] = 0; }
    }
    __syncthreads();

    prefetch_chunk(sb, 0, q0, q0, 0, tid);

    for (int unit = 0; unit < NUNITS; unit++) {
        const int d = unit >> 1, h = unit & 1;
        const int jstrip = (istrip + d) % NSTRIP;
        const int j0 = jstrip * SLEN + h * NT;
        if (tid < NT) sqc[tid] = g_sq[j0 + tid];

        float acc[4][4][4];
#pragma unroll
        for (int mb = 0; mb < 4; mb++)
#pragma unroll
            for (int nb = 0; nb < 4; nb++)
#pragma unroll
                for (int r = 0; r < 4; r++) acc[mb][nb][r] = 0.f;

        for (int kc = 0; kc < NCHUNK; kc++) {
            if (kc + 1 < NCHUNK) {
                prefetch_chunk(sb, (kc + 1) & 1, q0, j0, kc + 1, tid);
                asm volatile("cp.async.wait_group 1;" ::: "memory");
            } else if (unit + 1 < NUNITS) {
                int dn = (unit + 1) >> 1, hn = (unit + 1) & 1;
                int j0n = ((istrip + dn) % NSTRIP) * SLEN + hn * NT;
                prefetch_chunk(sb, 0, q0, j0n, 0, tid);
                asm volatile("cp.async.wait_group 1;" ::: "memory");
            } else {
                asm volatile("cp.async.wait_group 0;" ::: "memory");
            }
            __syncthreads();

            uint32_t stg = sb + (kc & 1) * ST_BYTES;
            uint32_t ab = stg, bb = stg + 32768;
#pragma unroll
            for (int k16 = 0; k16 < 4; k16++) {
                int u = k16 * 2;
                uint32_t a[4][4], b[4][2];
#pragma unroll
                for (int mb = 0; mb < 4; mb++) {
                    int row = wm * 64 + mb * 16 + lrA;
                    ldsm_x4(a[mb], ab + row * 128 + (((u + luA) ^ (row & 7)) << 4));
                }
#pragma unroll
                for (int nbp = 0; nbp < 2; nbp++) {
                    int rowb = wn * 32 + (nbp * 2 + (l >> 4)) * 8 + (l & 7);
                    int ku = u + ((l >> 3) & 1);
                    uint32_t tmp[4];
                    ldsm_x4(tmp, bb + rowb * 128 + ((ku ^ (rowb & 7)) << 4));
                    b[nbp * 2][0] = tmp[0]; b[nbp * 2][1] = tmp[1];
                    b[nbp * 2 + 1][0] = tmp[2]; b[nbp * 2 + 1][1] = tmp[3];
                }
#pragma unroll
                for (int mb = 0; mb < 4; mb++)
#pragma unroll
                    for (int nb = 0; nb < 4; nb++)
                        mma16816(acc[mb][nb], a[mb], b[nb]);
            }
            __syncthreads();
        }

        // ---- dump dots (fp16) transposed: dsh[n][q] ----
#pragma unroll
        for (int mb = 0; mb < 4; mb++)
#pragma unroll
            for (int nb = 0; nb < 4; nb++) {
                int q = wm * 64 + mb * 16 + (l >> 2);
                int n = wn * 32 + nb * 8 + (l & 3) * 2;
                dsh[(size_t)n * DSH + q]           = __float2half_rn(acc[mb][nb][0]);
                dsh[(size_t)(n + 1) * DSH + q]     = __float2half_rn(acc[mb][nb][1]);
                dsh[(size_t)n * DSH + q + 8]       = __float2half_rn(acc[mb][nb][2]);
                dsh[(size_t)(n + 1) * DSH + q + 8] = __float2half_rn(acc[mb][nb][3]);
            }
        __syncthreads();

        if (tid < MT) {
            // ---- row scan: 8-blocked screening ----
            for (int n0 = 0; n0 < NT; n0 += 8) {
                float dd[8];
                bool any = false;
#pragma unroll
                for (int i = 0; i < 8; i++) {
                    dd[i] = sqq + sqc[n0 + i]
                          - 2.f * __half2float(dsh[(size_t)(n0 + i) * DSH + tid]);
                    any |= (dd[i] < kmax);
                }
                if (any) {
#pragma unroll
                    for (int i = 0; i < 8; i++)
                        if (dd[i] < kmax) INSERT16(dd[i], j0 + n0 + i, kdp, kip, kmax, kpos);
                }
            }
        } else if (tid < MT + NT && d > 0) {
            // ---- col scan: fresh top-16, half2-vectorized screening ----
            int c = tid - MT;
            float sc = sqc[c];
            float ckd[T_SEL]; int cki[T_SEL];
#pragma unroll
            for (int t = 0; t < T_SEL; t++) { ckd[t] = INFINITY; cki[t] = 0; }
            float cmax = INFINITY; int cpos = 0;
            const __half* drow = dsh + (size_t)c * DSH;
            for (int q2 = 0; q2 < MT; q2 += 8) {
                float dd[8];
                bool any = false;
#pragma unroll
                for (int i = 0; i < 4; i++) {
                    __half2 h2 = *(const __half2*)(drow + q2 + 2 * i);
                    float2 f = __half22float2(h2);
                    dd[2 * i]     = sc + sqr[q2 + 2 * i]     - 2.f * f.x;
                    dd[2 * i + 1] = sc + sqr[q2 + 2 * i + 1] - 2.f * f.y;
                    any |= (dd[2 * i] < cmax) | (dd[2 * i + 1] < cmax);
                }
                if (any) {
#pragma unroll
                    for (int i = 0; i < 8; i++)
                        if (dd[i] < cmax) INSERT16(dd[i], q0 + q2 + i, ckd, cki, cmax, cpos);
                }
            }
            size_t base = (((size_t)jstrip * NSLOT + (d - 1)) * T_SEL) * SLEN + h * NT + c;
#pragma unroll
            for (int t = 0; t < T_SEL; t++) {
                g_part_d[base + (size_t)t * SLEN] = ckd[t];
                g_part_i[base + (size_t)t * SLEN] = cki[t];
            }
        }
        __syncthreads();
    }

    if (tid < MT) {
        size_t base = (size_t)istrip * T_SEL * SLEN + tid;
#pragma unroll
        for (int t = 0; t < T_SEL; t++) {
            g_loc_d[base + (size_t)t * SLEN] = kdp[t];
            g_loc_i[base + (size_t)t * SLEN] = kip[t];
        }
    }
}

// ---------------- merge: 4 subs per query, smem partials --------------------
__global__ __launch_bounds__(1024)
void merge_kernel() {
    extern __shared__ char msm[];
    float* pd = (float*)msm;                         // [3][T_SEL][SLEN]
    int*   pi = (int*)(msm + 3 * T_SEL * SLEN * 4);  // [3][T_SEL][SLEN]

    const int strip = blockIdx.x;
    const int tid = threadIdx.x;
    const int sub = tid >> 8, q = tid & 255;

    float kd[T_SEL]; int ki[T_SEL];
    if (sub == 0) {
        size_t lb = (size_t)strip * T_SEL * SLEN + q;
#pragma unroll
        for (int t = 0; t < T_SEL; t++) {
            kd[t] = g_loc_d[lb + (size_t)t * SLEN];
            ki[t] = g_loc_i[lb + (size_t)t * SLEN];
        }
    } else {
#pragma unroll
        for (int t = 0; t < T_SEL; t++) { kd[t] = INFINITY; ki[t] = 0; }
    }
    float kmax = kd[0]; int kpos = 0;
#pragma unroll
    for (int t = 1; t < T_SEL; t++)
        if (kd[t] > kmax) { kmax = kd[t]; kpos = t; }

    const int s0 = (sub == 0) ? 0 : 15 + (sub - 1) * 16;
    const int s1 = (sub == 0) ? 15 : s0 + 16;
    for (int s = s0; s < s1; s++) {
        size_t base = (((size_t)strip * NSLOT + s) * T_SEL) * SLEN + q;
#pragma unroll
        for (int t0 = 0; t0 < T_SEL; t0 += 8) {
            float dv[8];
            bool any = false;
#pragma unroll
            for (int i = 0; i < 8; i++) {
                dv[i] = g_part_d[base + (size_t)(t0 + i) * SLEN];
                any |= (dv[i] < kmax);
            }
            if (any) {
#pragma unroll
                for (int i = 0; i < 8; i++)
                    if (dv[i] < kmax) {
                        int ii = g_part_i[base + (size_t)(t0 + i) * SLEN];
                        INSERT16(dv[i], ii, kd, ki, kmax, kpos);
                    }
            }
        }
    }

    if (sub > 0) {
#pragma unroll
        for (int t = 0; t < T_SEL; t++) {
            pd[((sub - 1) * T_SEL + t) * SLEN + q] = kd[t];
            pi[((sub - 1) * T_SEL + t) * SLEN + q] = ki[t];
        }
    }
    __syncthreads();

    if (sub == 0) {
#pragma unroll
        for (int j = 0; j < 3; j++)
#pragma unroll
            for (int t = 0; t < T_SEL; t++) {
                float dv = pd[(j * T_SEL + t) * SLEN + q];
                if (dv < kmax) {
                    int ii = pi[(j * T_SEL + t) * SLEN + q];
                    INSERT16(dv, ii, kd, ki, kmax, kpos);
                }
            }
        size_t ob = (size_t)(strip * SLEN + q) * T_SEL;
#pragma unroll
        for (int t = 0; t < T_SEL; t++) g_mrg_i[ob + t] = ki[t];
    }
}

// ---------------- refine: exact fp32 on 16 candidates, 2-way ILP ------------
__global__ __launch_bounds__(256)
void refine_kernel(float* __restrict__ out) {
    const int warp = threadIdx.x >> 5, l = threadIdx.x & 31;
    const int q = blockIdx.x * 8 + warp;
    __shared__ float sd[8][T_SEL];
    __shared__ int   si[8][T_SEL];
    if (q >= N_PTS) return;

    const __half2* qh = (const __half2*)(g_hi + (size_t)q * C_DIM);
    const __half2* ql = (const __half2*)(g_lo + (size_t)q * C_DIM);
    float qx[16];
#pragma unroll
    for (int i = 0; i < 8; i++) {
        float2 h = __half22float2(qh[l + 32 * i]);
        float2 lo = __half22float2(ql[l + 32 * i]);
        qx[2 * i] = h.x + lo.x;
        qx[2 * i + 1] = h.y + lo.y;
    }
    float sqq = g_sq[q];

    for (int c = 0; c < T_SEL; c += 2) {
        int i0 = g_mrg_i[(size_t)q * T_SEL + c];
        int i1 = g_mrg_i[(size_t)q * T_SEL + c + 1];
        const __half2* ch0 = (const __half2*)(g_hi + (size_t)i0 * C_DIM);
        const __half2* cl0 = (const __half2*)(g_lo + (size_t)i0 * C_DIM);
        const __half2* ch1 = (const __half2*)(g_hi + (size_t)i1 * C_DIM);
        const __half2* cl1 = (const __half2*)(g_lo + (size_t)i1 * C_DIM);
        float a0 = 0.f, a1 = 0.f;
#pragma unroll
        for (int i = 0; i < 8; i++) {
            float2 h0 = __half22float2(ch0[l + 32 * i]);
            float2 lo0 = __half22float2(cl0[l + 32 * i]);
            float2 h1 = __half22float2(ch1[l + 32 * i]);
            float2 lo1 = __half22float2(cl1[l + 32 * i]);
            a0 = fmaf(qx[2 * i], h0.x + lo0.x, a0);
            a0 = fmaf(qx[2 * i + 1], h0.y + lo0.y, a0);
            a1 = fmaf(qx[2 * i], h1.x + lo1.x, a1);
            a1 = fmaf(qx[2 * i + 1], h1.y + lo1.y, a1);
        }
#pragma unroll
        for (int o = 16; o > 0; o >>= 1) {
            a0 += __shfl_xor_sync(0xFFFFFFFF, a0, o);
            a1 += __shfl_xor_sync(0xFFFFFFFF, a1, o);
        }
        if (l == 0) {
            sd[warp][c]     = sqq + g_sq[i0] - 2.f * a0;
            si[warp][c]     = i0;
            sd[warp][c + 1] = sqq + g_sq[i1] - 2.f * a1;
            si[warp][c + 1] = i1;
        }
    }
    __syncwarp();

    if (l == 0) {
        float kd[KNN]; int ki[KNN];
#pragma unroll
        for (int t = 0; t < KNN; t++) { kd[t] = INFINITY; ki[t] = 0; }
        float kmax = INFINITY; int kpos = 0;
#pragma unroll
        for (int c = 0; c < T_SEL; c++) {
            float dd = sd[warp][c];
            if (dd < kmax) {
                kd[kpos] = dd; ki[kpos] = si[warp][c];
                kmax = kd[0]; kpos = 0;
#pragma unroll
                for (int t = 1; t < KNN; t++)
                    if (kd[t] > kmax) { kmax = kd[t]; kpos = t; }
            }
        }
        int cnt[NCLS];
#pragma unroll
        for (int c = 0; c < NCLS; c++) cnt[c] = 0;
#pragma unroll
        for (int t = 0; t < KNN; t++) cnt[g_label[ki[t]]]++;
        float s = 0.f;
#pragma unroll
        for (int c = 0; c < NCLS; c++) {
            if (cnt[c] > 0) {
                float p = (float)cnt[c] * (1.f / 9.f);
                s -= p * logf(p + 1e-6f);
            }
        }
        out[q] = s * (1.f / logf(19.f));
    }
}

// ---------------- launch ----------------------------------------------------
extern "C" void kernel_launch(void* const* d_in, const int* in_sizes, int n_in,
                              void* d_out, int out_size) {
    const float* feats = (const float*)d_in[0];
    const float* outs  = (const float*)d_in[1];
    float* out = (float*)d_out;

    cudaFuncSetAttribute(phase1_kernel,
                         cudaFuncAttributeMaxDynamicSharedMemorySize, DYNSMEM);
    cudaFuncSetAttribute(merge_kernel,
                         cudaFuncAttributeMaxDynamicSharedMemorySize, 2 * MERGE_SMEM);

    cudaMemsetAsync(out, 0, (size_t)out_size * sizeof(float), 0);
    prep_kernel<<<(N_PAD + 255) / 256, 256>>>(feats, outs);
    {
        dim3 g(N_PAD / 32, C_DIM / 32), b(32, 32);
        split_kernel<<<g, b>>>(feats);
    }
    phase1_kernel<<<NSTRIP, NTH, DYNSMEM>>>();
    merge_kernel<<<NSTRIP, 1024, 2 * MERGE_SMEM>>>();
    refine_kernel<<<(N_PTS + 7) / 8, 256>>>(out);
}

// round 8
// speedup vs baseline: 4.2439x; 1.0290x over previous
#include <cuda_runtime.h>
#include <cuda_fp16.h>
#include <math.h>
#include <stdint.h>

#define N_PTS  32400
#define NSTRIP 127
#define SLEN   256
#define N_PAD  (NSTRIP * SLEN)   // 32512
#define C_DIM  512
#define NCLS   19
#define KNN    9
#define NSLOT  63
#define T_SEL  16

#define MT 256
#define NT 128
#define KC 64
#define NCHUNK (C_DIM / KC)      // 8
#define NTH 512
#define NUNITS 128
#define NBLK   (NSTRIP * 2)      // 254 row-blocks of 128 points
#define BLK_HALFS 8192           // 16 KB block = 128 rows x 64 halfs

// phase-1 smem
#define ST_BYTES 49152           // stage: A 32K (2 blocks) + B 16K
#define SM_DS   98304
#define DSH     270
#define SM_KD   167936
#define SM_KI   (SM_KD + 16384)
#define SM_SQC  (SM_KI + 16384)
#define SM_SQR  (SM_SQC + 512)
#define SM_MBAR (SM_SQR + 1024)
#define DYNSMEM (SM_MBAR + 2048)   // mbarriers + full 1024B alignment slack

#define MERGE_SMEM (3 * T_SEL * SLEN * 8)

// ---------------- device globals ----------------
// tiled + swizzled fp16 planes: [blk][kc][128 rows x 8 units x 8 halfs]
__device__ __align__(128) __half g_swh[(size_t)NBLK * NCHUNK * BLK_HALFS];
__device__ __align__(128) __half g_swl[(size_t)NBLK * NCHUNK * BLK_HALFS];
__device__ float  g_sq[N_PAD];
__device__ int    g_label[N_PTS];
__device__ float  g_part_d[(size_t)NSTRIP * NSLOT * T_SEL * SLEN];
__device__ int    g_part_i[(size_t)NSTRIP * NSLOT * T_SEL * SLEN];
__device__ float  g_loc_d[(size_t)NSTRIP * T_SEL * SLEN];
__device__ int    g_loc_i[(size_t)NSTRIP * T_SEL * SLEN];
__device__ int    g_mrg_i[(size_t)N_PAD * T_SEL];

// ---------------- helpers ----------------
__device__ __forceinline__ uint32_t smem_u32(const void* p) {
    uint32_t a;
    asm("{ .reg .u64 t; cvta.to.shared.u64 t, %1; cvt.u32.u64 %0, t; }" : "=r"(a) : "l"(p));
    return a;
}
__device__ __forceinline__ void ldsm_x4(uint32_t* r, uint32_t a) {
    asm volatile("ldmatrix.sync.aligned.m8n8.x4.shared.b16 {%0,%1,%2,%3}, [%4];"
                 : "=r"(r[0]), "=r"(r[1]), "=r"(r[2]), "=r"(r[3]) : "r"(a));
}
__device__ __forceinline__ void mma16816(float* c, const uint32_t* a, const uint32_t* b) {
    asm volatile("mma.sync.aligned.m16n8k16.row.col.f32.f16.f16.f32 "
                 "{%0,%1,%2,%3}, {%4,%5,%6,%7}, {%8,%9}, {%0,%1,%2,%3};"
                 : "+f"(c[0]), "+f"(c[1]), "+f"(c[2]), "+f"(c[3])
                 : "r"(a[0]), "r"(a[1]), "r"(a[2]), "r"(a[3]), "r"(b[0]), "r"(b[1]));
}
__device__ __forceinline__ void bulk_g2s(uint32_t dst, const __half* src,
                                         uint32_t bytes, uint32_t mbar) {
    asm volatile("cp.async.bulk.shared::cluster.global.mbarrier::complete_tx::bytes "
                 "[%0], [%1], %2, [%3];"
                 :: "r"(dst), "l"(__cvta_generic_to_global(src)), "r"(bytes), "r"(mbar)
                 : "memory");
}
#define MBAR_INIT(mb, c)  asm volatile("mbarrier.init.shared.b64 [%0], %1;" :: "r"(mb), "r"(c) : "memory")
#define MBAR_WAIT(mb, ph) do {                                                   \
    uint32_t _mb = (mb), _ph = (ph), _done;                                      \
    asm volatile("{ .reg .pred p; mbarrier.try_wait.parity.acquire.cta.shared::cta.b64 p, [%1], %2; selp.b32 %0, 1, 0, p; }" \
        : "=r"(_done) : "r"(_mb), "r"(_ph) : "memory");                          \
    if (!_done) {                                                                \
        asm volatile("{ .reg .pred P1; WL_%=: mbarrier.try_wait.parity.acquire.cta.shared::cta.b64 P1, [%0], %1, 0x989680; @P1 bra.uni WD_%=; bra.uni WL_%=; WD_%=: }" \
            :: "r"(_mb), "r"(_ph) : "memory");                                   \
    }                                                                            \
} while (0)

#define INSERT16(dd, ii, kdp, kip, kmax, kpos)                                   \
    do {                                                                         \
        (kdp)[kpos] = (dd); (kip)[kpos] = (ii);                                  \
        kmax = (kdp)[0]; kpos = 0;                                               \
        _Pragma("unroll")                                                        \
        for (int _t = 1; _t < T_SEL; _t++)                                       \
            if ((kdp)[_t] > kmax) { kmax = (kdp)[_t]; kpos = _t; }               \
    } while (0)

// tiled-swizzled half-index for point n, chunk i, lane l (reads __half2)
__device__ __forceinline__ size_t sw_off(int n, int chunk, int l) {
    int blk = n >> 7, r = n & 127;
    return ((size_t)(blk * NCHUNK + chunk)) * BLK_HALFS + r * 64
         + (((l >> 2) ^ (r & 7)) << 3) + ((l & 3) << 1);
}

// ---------------- prep ----------------
__global__ void prep_kernel(const float* __restrict__ feats,
                            const float* __restrict__ outs) {
    int n = blockIdx.x * blockDim.x + threadIdx.x;
    if (n >= N_PAD) return;
    if (n >= N_PTS) { g_sq[n] = 1e30f; return; }
    float s = 0.f;
#pragma unroll 8
    for (int c = 0; c < C_DIM; c++) {
        float v = feats[(size_t)c * N_PTS + n];
        s = fmaf(v, v, s);
    }
    g_sq[n] = s;
    float best = outs[n];
    int bl = 0;
#pragma unroll
    for (int c = 1; c < NCLS; c++) {
        float v = outs[(size_t)c * N_PTS + n];
        if (v > best) { best = v; bl = c; }
    }
    g_label[n] = bl;
}

// ---------------- transpose + fp16 hi/lo split into tiled layout ------------
__global__ void split_kernel(const float* __restrict__ feats) {
    __shared__ float t[32][33];
    int n0 = blockIdx.x * 32, c0 = blockIdx.y * 32;
    int n = n0 + threadIdx.x;
    t[threadIdx.y][threadIdx.x] = (n < N_PTS) ? feats[(size_t)(c0 + threadIdx.y) * N_PTS + n] : 0.f;
    __syncthreads();
    int np = n0 + threadIdx.y, cp = c0 + threadIdx.x;
    float x = t[threadIdx.x][threadIdx.y];
    __half hi = __float2half_rn(x);
    __half lo = __float2half_rn(x - __half2float(hi));
    int blk = np >> 7, r = np & 127;
    int kc2 = cp >> 6, u = (cp >> 3) & 7, b = cp & 7;
    size_t off = ((size_t)(blk * NCHUNK + kc2)) * BLK_HALFS + r * 64
               + ((u ^ (r & 7)) << 3) + b;
    g_swh[off] = hi; g_swl[off] = lo;
}

// ---------------- bulk chunk issue (single thread) ---------------------------
__device__ __forceinline__ void issue_chunk(uint32_t sb, int stage,
                                            int iblk2, int jblk, int kc) {
    uint32_t st = sb + stage * ST_BYTES;
    uint32_t mbar = sb + SM_MBAR + 8 * stage;
    const __half* a0 = g_swh + ((size_t)(iblk2 * NCHUNK + kc)) * BLK_HALFS;
    const __half* a1 = g_swh + ((size_t)((iblk2 + 1) * NCHUNK + kc)) * BLK_HALFS;
    const __half* bb = g_swh + ((size_t)(jblk * NCHUNK + kc)) * BLK_HALFS;
    asm volatile("fence.proxy.async.shared::cta;" ::: "memory");
    asm volatile("mbarrier.arrive.expect_tx.shared.b64 _, [%0], %1;"
                 :: "r"(mbar), "r"(49152u) : "memory");
    bulk_g2s(st, a0, 16384, mbar);
    bulk_g2s(st + 16384, a1, 16384, mbar);
    bulk_g2s(st + 32768, bb, 16384, mbar);
}

// ---------------- phase 1: hh GEMM + bidirectional top-16 -------------------
__global__ __launch_bounds__(NTH, 1)
void phase1_kernel() {
    extern __shared__ char smraw[];
    uint32_t sbr = smem_u32(smraw);
    uint32_t sb = (sbr + 1023u) & ~1023u;
    char* smem = smraw + (sb - sbr);

    const int tid = threadIdx.x;
    const int l = tid & 31, w = tid >> 5;
    const int wm = w >> 2, wn = w & 3;
    const int istrip = blockIdx.x;
    const int iblk2 = istrip * 2;
    const int q0 = istrip * SLEN;
    const int lrA = l & 15, luA = l >> 4;

    float* kdp = (float*)(smem + SM_KD) + tid * T_SEL;
    int*   kip = (int*)(smem + SM_KI) + tid * T_SEL;
    float* sqc = (float*)(smem + SM_SQC);
    float* sqr = (float*)(smem + SM_SQR);
    __half* dsh = (__half*)(smem + SM_DS);

    float sqq = 0.f, kmax = INFINITY;
    int kpos = 0;
    if (tid < MT) {
        sqq = g_sq[q0 + tid];
        sqr[tid] = sqq;
#pragma unroll
        for (int t = 0; t < T_SEL; t++) { kdp[t] = INFINITY; kip[t] = 0; }
    }
    if (tid == 0) {
        MBAR_INIT(sb + SM_MBAR, 1);
        MBAR_INIT(sb + SM_MBAR + 8, 1);
    }
    __syncthreads();
    int ph0 = 0, ph1 = 0;

    if (tid == 0) issue_chunk(sb, 0, iblk2, iblk2, 0);   // unit0: d=0,h=0

    for (int unit = 0; unit < NUNITS; unit++) {
        const int d = unit >> 1, h = unit & 1;
        const int jstrip = (istrip + d) % NSTRIP;
        const int jblk = jstrip * 2 + h;
        const int j0 = jstrip * SLEN + h * NT;
        if (tid < NT) sqc[tid] = g_sq[j0 + tid];

        float acc[4][4][4];
#pragma unroll
        for (int mb = 0; mb < 4; mb++)
#pragma unroll
            for (int nb = 0; nb < 4; nb++)
#pragma unroll
                for (int r = 0; r < 4; r++) acc[mb][nb][r] = 0.f;

        for (int kc = 0; kc < NCHUNK; kc++) {
            const int stage = kc & 1;
            if (tid == 0) {
                if (kc + 1 < NCHUNK) {
                    issue_chunk(sb, (kc + 1) & 1, iblk2, jblk, kc + 1);
                } else if (unit + 1 < NUNITS) {
                    int un = unit + 1, dn = un >> 1, hn = un & 1;
                    int jblkn = ((istrip + dn) % NSTRIP) * 2 + hn;
                    issue_chunk(sb, 0, iblk2, jblkn, 0);
                }
            }
            if (stage == 0) { MBAR_WAIT(sb + SM_MBAR, ph0); ph0 ^= 1; }
            else           { MBAR_WAIT(sb + SM_MBAR + 8, ph1); ph1 ^= 1; }

            uint32_t stg = sb + stage * ST_BYTES;
            uint32_t ab = stg, bb = stg + 32768;
#pragma unroll
            for (int k16 = 0; k16 < 4; k16++) {
                int u = k16 * 2;
                uint32_t a[4][4], b[4][2];
#pragma unroll
                for (int mb = 0; mb < 4; mb++) {
                    int row = wm * 64 + mb * 16 + lrA;
                    ldsm_x4(a[mb], ab + row * 128 + (((u + luA) ^ (row & 7)) << 4));
                }
#pragma unroll
                for (int nbp = 0; nbp < 2; nbp++) {
                    int rowb = wn * 32 + (nbp * 2 + (l >> 4)) * 8 + (l & 7);
                    int ku = u + ((l >> 3) & 1);
                    uint32_t tmp[4];
                    ldsm_x4(tmp, bb + rowb * 128 + ((ku ^ (rowb & 7)) << 4));
                    b[nbp * 2][0] = tmp[0]; b[nbp * 2][1] = tmp[1];
                    b[nbp * 2 + 1][0] = tmp[2]; b[nbp * 2 + 1][1] = tmp[3];
                }
#pragma unroll
                for (int mb = 0; mb < 4; mb++)
#pragma unroll
                    for (int nb = 0; nb < 4; nb++)
                        mma16816(acc[mb][nb], a[mb], b[nb]);
            }
            __syncthreads();
        }

        // ---- dump dots (fp16) transposed: dsh[n][q] ----
#pragma unroll
        for (int mb = 0; mb < 4; mb++)
#pragma unroll
            for (int nb = 0; nb < 4; nb++) {
                int q = wm * 64 + mb * 16 + (l >> 2);
                int n = wn * 32 + nb * 8 + (l & 3) * 2;
                dsh[(size_t)n * DSH + q]           = __float2half_rn(acc[mb][nb][0]);
                dsh[(size_t)(n + 1) * DSH + q]     = __float2half_rn(acc[mb][nb][1]);
                dsh[(size_t)n * DSH + q + 8]       = __float2half_rn(acc[mb][nb][2]);
                dsh[(size_t)(n + 1) * DSH + q + 8] = __float2half_rn(acc[mb][nb][3]);
            }
        __syncthreads();

        if (tid < MT) {
            // ---- row scan: 8-blocked screening ----
            for (int n0 = 0; n0 < NT; n0 += 8) {
                float dd[8];
                bool any = false;
#pragma unroll
                for (int i = 0; i < 8; i++) {
                    dd[i] = sqq + sqc[n0 + i]
                          - 2.f * __half2float(dsh[(size_t)(n0 + i) * DSH + tid]);
                    any |= (dd[i] < kmax);
                }
                if (any) {
#pragma unroll
                    for (int i = 0; i < 8; i++)
                        if (dd[i] < kmax) INSERT16(dd[i], j0 + n0 + i, kdp, kip, kmax, kpos);
                }
            }
        } else if (tid < MT + NT && d > 0) {
            // ---- col scan: fresh top-16, half2-vectorized ----
            int c = tid - MT;
            float sc = sqc[c];
            float ckd[T_SEL]; int cki[T_SEL];
#pragma unroll
            for (int t = 0; t < T_SEL; t++) { ckd[t] = INFINITY; cki[t] = 0; }
            float cmax = INFINITY; int cpos = 0;
            const __half* drow = dsh + (size_t)c * DSH;
            for (int q2 = 0; q2 < MT; q2 += 8) {
                float dd[8];
                bool any = false;
#pragma unroll
                for (int i = 0; i < 4; i++) {
                    __half2 h2 = *(const __half2*)(drow + q2 + 2 * i);
                    float2 f = __half22float2(h2);
                    dd[2 * i]     = sc + sqr[q2 + 2 * i]     - 2.f * f.x;
                    dd[2 * i + 1] = sc + sqr[q2 + 2 * i + 1] - 2.f * f.y;
                    any |= (dd[2 * i] < cmax) | (dd[2 * i + 1] < cmax);
                }
                if (any) {
#pragma unroll
                    for (int i = 0; i < 8; i++)
                        if (dd[i] < cmax) INSERT16(dd[i], q0 + q2 + i, ckd, cki, cmax, cpos);
                }
            }
            size_t base = (((size_t)jstrip * NSLOT + (d - 1)) * T_SEL) * SLEN + h * NT + c;
#pragma unroll
            for (int t = 0; t < T_SEL; t++) {
                g_part_d[base + (size_t)t * SLEN] = ckd[t];
                g_part_i[base + (size_t)t * SLEN] = cki[t];
            }
        }
        __syncthreads();
    }

    if (tid < MT) {
        size_t base = (size_t)istrip * T_SEL * SLEN + tid;
#pragma unroll
        for (int t = 0; t < T_SEL; t++) {
            g_loc_d[base + (size_t)t * SLEN] = kdp[t];
            g_loc_i[base + (size_t)t * SLEN] = kip[t];
        }
    }
}

// ---------------- merge: 4 subs per query, smem partials --------------------
__global__ __launch_bounds__(1024)
void merge_kernel() {
    extern __shared__ char msm[];
    float* pd = (float*)msm;
    int*   pi = (int*)(msm + 3 * T_SEL * SLEN * 4);

    const int strip = blockIdx.x;
    const int tid = threadIdx.x;
    const int sub = tid >> 8, q = tid & 255;

    float kd[T_SEL]; int ki[T_SEL];
    if (sub == 0) {
        size_t lb = (size_t)strip * T_SEL * SLEN + q;
#pragma unroll
        for (int t = 0; t < T_SEL; t++) {
            kd[t] = g_loc_d[lb + (size_t)t * SLEN];
            ki[t] = g_loc_i[lb + (size_t)t * SLEN];
        }
    } else {
#pragma unroll
        for (int t = 0; t < T_SEL; t++) { kd[t] = INFINITY; ki[t] = 0; }
    }
    float kmax = kd[0]; int kpos = 0;
#pragma unroll
    for (int t = 1; t < T_SEL; t++)
        if (kd[t] > kmax) { kmax = kd[t]; kpos = t; }

    const int s0 = (sub == 0) ? 0 : 15 + (sub - 1) * 16;
    const int s1 = (sub == 0) ? 15 : s0 + 16;
    for (int s = s0; s < s1; s++) {
        size_t base = (((size_t)strip * NSLOT + s) * T_SEL) * SLEN + q;
#pragma unroll
        for (int t0 = 0; t0 < T_SEL; t0 += 8) {
            float dv[8];
            bool any = false;
#pragma unroll
            for (int i = 0; i < 8; i++) {
                dv[i] = g_part_d[base + (size_t)(t0 + i) * SLEN];
                any |= (dv[i] < kmax);
            }
            if (any) {
#pragma unroll
                for (int i = 0; i < 8; i++)
                    if (dv[i] < kmax) {
                        int ii = g_part_i[base + (size_t)(t0 + i) * SLEN];
                        INSERT16(dv[i], ii, kd, ki, kmax, kpos);
                    }
            }
        }
    }

    if (sub > 0) {
#pragma unroll
        for (int t = 0; t < T_SEL; t++) {
            pd[((sub - 1) * T_SEL + t) * SLEN + q] = kd[t];
            pi[((sub - 1) * T_SEL + t) * SLEN + q] = ki[t];
        }
    }
    __syncthreads();

    if (sub == 0) {
#pragma unroll
        for (int j = 0; j < 3; j++)
#pragma unroll
            for (int t = 0; t < T_SEL; t++) {
                float dv = pd[(j * T_SEL + t) * SLEN + q];
                if (dv < kmax) {
                    int ii = pi[(j * T_SEL + t) * SLEN + q];
                    INSERT16(dv, ii, kd, ki, kmax, kpos);
                }
            }
        size_t ob = (size_t)(strip * SLEN + q) * T_SEL;
#pragma unroll
        for (int t = 0; t < T_SEL; t++) g_mrg_i[ob + t] = ki[t];
    }
}

// ---------------- refine: exact fp32 on 16 candidates, 2-way ILP ------------
__global__ __launch_bounds__(256)
void refine_kernel(float* __restrict__ out) {
    const int warp = threadIdx.x >> 5, l = threadIdx.x & 31;
    const int q = blockIdx.x * 8 + warp;
    __shared__ float sd[8][T_SEL];
    __shared__ int   si[8][T_SEL];
    if (q >= N_PTS) return;

    float qx[16];
#pragma unroll
    for (int i = 0; i < 8; i++) {
        size_t o = sw_off(q, i, l);
        float2 h = __half22float2(*(const __half2*)(g_swh + o));
        float2 lo = __half22float2(*(const __half2*)(g_swl + o));
        qx[2 * i] = h.x + lo.x;
        qx[2 * i + 1] = h.y + lo.y;
    }
    float sqq = g_sq[q];

    for (int c = 0; c < T_SEL; c += 2) {
        int i0 = g_mrg_i[(size_t)q * T_SEL + c];
        int i1 = g_mrg_i[(size_t)q * T_SEL + c + 1];
        float a0 = 0.f, a1 = 0.f;
#pragma unroll
        for (int i = 0; i < 8; i++) {
            size_t o0 = sw_off(i0, i, l);
            size_t o1 = sw_off(i1, i, l);
            float2 h0 = __half22float2(*(const __half2*)(g_swh + o0));
            float2 lo0 = __half22float2(*(const __half2*)(g_swl + o0));
            float2 h1 = __half22float2(*(const __half2*)(g_swh + o1));
            float2 lo1 = __half22float2(*(const __half2*)(g_swl + o1));
            a0 = fmaf(qx[2 * i], h0.x + lo0.x, a0);
            a0 = fmaf(qx[2 * i + 1], h0.y + lo0.y, a0);
            a1 = fmaf(qx[2 * i], h1.x + lo1.x, a1);
            a1 = fmaf(qx[2 * i + 1], h1.y + lo1.y, a1);
        }
#pragma unroll
        for (int o = 16; o > 0; o >>= 1) {
            a0 += __shfl_xor_sync(0xFFFFFFFF, a0, o);
            a1 += __shfl_xor_sync(0xFFFFFFFF, a1, o);
        }
        if (l == 0) {
            sd[warp][c]     = sqq + g_sq[i0] - 2.f * a0;
            si[warp][c]     = i0;
            sd[warp][c + 1] = sqq + g_sq[i1] - 2.f * a1;
            si[warp][c + 1] = i1;
        }
    }
    __syncwarp();

    if (l == 0) {
        float kd[KNN]; int ki[KNN];
#pragma unroll
        for (int t = 0; t < KNN; t++) { kd[t] = INFINITY; ki[t] = 0; }
        float kmax = INFINITY; int kpos = 0;
#pragma unroll
        for (int c = 0; c < T_SEL; c++) {
            float dd = sd[warp][c];
            if (dd < kmax) {
                kd[kpos] = dd; ki[kpos] = si[warp][c];
                kmax = kd[0]; kpos = 0;
#pragma unroll
                for (int t = 1; t < KNN; t++)
                    if (kd[t] > kmax) { kmax = kd[t]; kpos = t; }
            }
        }
        int cnt[NCLS];
#pragma unroll
        for (int c = 0; c < NCLS; c++) cnt[c] = 0;
#pragma unroll
        for (int t = 0; t < KNN; t++) cnt[g_label[ki[t]]]++;
        float s = 0.f;
#pragma unroll
        for (int c = 0; c < NCLS; c++) {
            if (cnt[c] > 0) {
                float p = (float)cnt[c] * (1.f / 9.f);
                s -= p * logf(p + 1e-6f);
            }
        }
        out[q] = s * (1.f / logf(19.f));
    }
}

// ---------------- launch ----------------------------------------------------
extern "C" void kernel_launch(void* const* d_in, const int* in_sizes, int n_in,
                              void* d_out, int out_size) {
    const float* feats = (const float*)d_in[0];
    const float* outs  = (const float*)d_in[1];
    float* out = (float*)d_out;

    cudaFuncSetAttribute(phase1_kernel,
                         cudaFuncAttributeMaxDynamicSharedMemorySize, DYNSMEM);
    cudaFuncSetAttribute(merge_kernel,
                         cudaFuncAttributeMaxDynamicSharedMemorySize, 2 * MERGE_SMEM);

    cudaMemsetAsync(out, 0, (size_t)out_size * sizeof(float), 0);
    prep_kernel<<<(N_PAD + 255) / 256, 256>>>(feats, outs);
    {
        dim3 g(N_PAD / 32, C_DIM / 32), b(32, 32);
        split_kernel<<<g, b>>>(feats);
    }
    phase1_kernel<<<NSTRIP, NTH, DYNSMEM>>>();
    merge_kernel<<<NSTRIP, 1024, 2 * MERGE_SMEM>>>();
    refine_kernel<<<(N_PTS + 7) / 8, 256>>>(out);
}